// round 1
// baseline (speedup 1.0000x reference)
#include <cuda_runtime.h>
#include <math.h>

// Problem constants
#define BB 8
#define NN 7168
#define NTOK (BB*NN)            // 57344
#define UU 49152
#define CLS 68                  // padded smem row stride (floats)
#define GRID 148
#define THREADS 512
#define WARPS (THREADS/32)
#define STRIDE (GRID*WARPS)     // 2368

__device__ float g_z[(size_t)NTOK * 64];   // attention output scratch (pre-LN)

__device__ __forceinline__ float warpSum(float v) {
    v += __shfl_xor_sync(0xffffffffu, v, 16);
    v += __shfl_xor_sync(0xffffffffu, v, 8);
    v += __shfl_xor_sync(0xffffffffu, v, 4);
    v += __shfl_xor_sync(0xffffffffu, v, 2);
    v += __shfl_xor_sync(0xffffffffu, v, 1);
    return v;
}

// ---------------------------------------------------------------------------
// Kernel A: bunched grouped cross-attention -> g_z
// smem layout (floats):
//   [0,4096)      WqS   (natural [e][d])
//   [4096,8192)   WkTS  (transposed: [d][e])
//   [8192,12288)  WvS   (natural [e][d])
//   [12288..]     bqS(64) bkS(64) bvS(64)
//   [12480..]     per-warp: uS 16*68, rwS 4*68, lgS 64, atS 64  (=1488 fl/warp)
// total = 12480 + 16*1488 = 36288 floats = 145152 B
// ---------------------------------------------------------------------------
__global__ __launch_bounds__(THREADS, 1)
void attn_kernel(const float* __restrict__ u, const float* __restrict__ x,
                 const float* __restrict__ Wk, const float* __restrict__ bk,
                 const float* __restrict__ Wq, const float* __restrict__ bq,
                 const float* __restrict__ Wv, const float* __restrict__ bv)
{
    extern __shared__ float sm[];
    float* WqS  = sm;
    float* WkTS = sm + 4096;
    float* WvS  = sm + 8192;
    float* bqS  = sm + 12288;
    float* bkS  = sm + 12352;
    float* bvS  = sm + 12416;

    const int tid = threadIdx.x;
    const int wid = tid >> 5;
    const int L   = tid & 31;

    float* warpS = sm + 12480 + wid * 1488;
    float* uS  = warpS;          // 16 x 68
    float* rwS = warpS + 1088;   // 4 x 68 (r, later w)
    float* lgS = warpS + 1360;   // 64 logits
    float* atS = warpS + 1424;   // 64 attn

    for (int i = tid; i < 4096; i += THREADS) {
        WqS[i] = Wq[i];
        WvS[i] = Wv[i];
        WkTS[(i & 63) * 64 + (i >> 6)] = Wk[i];   // transpose Wk
    }
    if (tid < 64) { bqS[tid] = bq[tid]; bkS[tid] = bk[tid]; bvS[tid] = bv[tid]; }
    __syncthreads();

    for (int tok = blockIdx.x * WARPS + wid; tok < NTOK; tok += STRIDE) {
        const int b = tok / NN;
        const int n = tok - b * NN;

        int to, urow;
        if (n < 4096) {                       // bunch 0: rel=2, to=4
            to = 4;
            urow = (n < 2048) ? (n * 4) : (24576 + (n - 2048) * 4);
        } else if (n < 6144) {                // bunch 1: rel=4, to=8
            int m = n - 4096;
            to = 8;
            urow = (m < 1024) ? (8192 + m * 8) : (32768 + (m - 1024) * 8);
        } else {                              // bunch 2: rel=8, to=16
            int m = n - 6144;
            to = 16;
            urow = (m < 512) ? (16384 + m * 16) : (40960 + (m - 512) * 16);
        }

        const float* xr = x + (size_t)tok * 64;
        const float* ur = u + ((size_t)b * UU + (size_t)urow) * 64;

        float x0 = xr[L], x1 = xr[L + 32];

        // stage u tile (contiguous to*64 floats) into padded smem
        const int cnt = to * 64;
        #pragma unroll 4
        for (int i = L; i < cnt; i += 32)
            uS[(i >> 6) * CLS + (i & 63)] = ur[i];

        // q = x @ Wq + bq  (lane owns channels L, L+32)
        float q0 = bqS[L], q1 = bqS[L + 32];
        #pragma unroll 8
        for (int e = 0; e < 32; e++) {
            float xb = __shfl_sync(0xffffffffu, x0, e);
            q0 = fmaf(xb, WqS[e * 64 + L], q0);
            q1 = fmaf(xb, WqS[e * 64 + L + 32], q1);
        }
        #pragma unroll 8
        for (int e = 0; e < 32; e++) {
            float xb = __shfl_sync(0xffffffffu, x1, e);
            q0 = fmaf(xb, WqS[(e + 32) * 64 + L], q0);
            q1 = fmaf(xb, WqS[(e + 32) * 64 + L + 32], q1);
        }

        // r[g][e] = sum_{d in g} Wk[e][d]*q[d];  s[g] = sum_{d in g} bk[d]*q[d]
        float r0[4], r1[4], s[4];
        #pragma unroll
        for (int g = 0; g < 4; g++) { r0[g] = 0.f; r1[g] = 0.f; s[g] = 0.f; }
        #pragma unroll
        for (int g = 0; g < 4; g++) {
            #pragma unroll
            for (int dd = 0; dd < 16; dd++) {
                const int d = g * 16 + dd;
                float qb = (d < 32) ? __shfl_sync(0xffffffffu, q0, d)
                                    : __shfl_sync(0xffffffffu, q1, d - 32);
                r0[g] = fmaf(WkTS[d * 64 + L], qb, r0[g]);
                r1[g] = fmaf(WkTS[d * 64 + L + 32], qb, r1[g]);
                s[g]  = fmaf(bkS[d], qb, s[g]);
            }
            rwS[g * CLS + L]      = r0[g];
            rwS[g * CLS + L + 32] = r1[g];
        }
        __syncwarp();

        // logits[t][g] = (u[t] . r[g] + s[g]) * scale
        const int P = to * 4;
        #pragma unroll
        for (int rep = 0; rep < 2; rep++) {
            int p = L + rep * 32;
            if (p < P) {
                int t = p >> 2, g = p & 3;
                float acc = s[0];
                if (g == 1) acc = s[1]; else if (g == 2) acc = s[2]; else if (g == 3) acc = s[3];
                const float4* up = (const float4*)(uS  + t * CLS);
                const float4* rp = (const float4*)(rwS + g * CLS);
                #pragma unroll
                for (int e4 = 0; e4 < 16; e4++) {
                    float4 a = up[e4], bb = rp[e4];
                    acc = fmaf(a.x, bb.x, acc);
                    acc = fmaf(a.y, bb.y, acc);
                    acc = fmaf(a.z, bb.z, acc);
                    acc = fmaf(a.w, bb.w, acc);
                }
                lgS[p] = acc * 0.125f;
            }
        }
        __syncwarp();

        // softmax over t (per group): 4 lanes do it serially (tiny)
        if (L < 4) {
            float mx = -1e30f;
            for (int t = 0; t < to; t++) mx = fmaxf(mx, lgS[t * 4 + L]);
            float ss = 0.f;
            for (int t = 0; t < to; t++) {
                float e = expf(lgS[t * 4 + L] - mx);
                atS[t * 4 + L] = e;
                ss += e;
            }
            float is = 1.f / ss;
            for (int t = 0; t < to; t++) atS[t * 4 + L] *= is;
        }
        __syncwarp();

        // w[g][e] = sum_t attn[t][g] * u[t][e]
        float w0[4] = {0.f,0.f,0.f,0.f}, w1[4] = {0.f,0.f,0.f,0.f};
        for (int t = 0; t < to; t++) {
            float4 a = *(const float4*)(atS + t * 4);
            float uu0 = uS[t * CLS + L], uu1 = uS[t * CLS + L + 32];
            w0[0] = fmaf(a.x, uu0, w0[0]); w1[0] = fmaf(a.x, uu1, w1[0]);
            w0[1] = fmaf(a.y, uu0, w0[1]); w1[1] = fmaf(a.y, uu1, w1[1]);
            w0[2] = fmaf(a.z, uu0, w0[2]); w1[2] = fmaf(a.z, uu1, w1[2]);
            w0[3] = fmaf(a.w, uu0, w0[3]); w1[3] = fmaf(a.w, uu1, w1[3]);
        }
        __syncwarp();   // all logits reads of rwS are done; safe to overwrite
        #pragma unroll
        for (int g = 0; g < 4; g++) {
            rwS[g * CLS + L]      = w0[g];
            rwS[g * CLS + L + 32] = w1[g];
        }
        __syncwarp();

        // out[d] = w[g(d)] . Wv[:,d] + bv[d]
        const int ga = L >> 4;   // group of channel L (0/1); channel L+32 -> ga+2
        float o0 = bvS[L], o1 = bvS[L + 32];
        #pragma unroll 8
        for (int e = 0; e < 64; e++) {
            o0 = fmaf(rwS[ga * CLS + e],       WvS[e * 64 + L],      o0);
            o1 = fmaf(rwS[(ga + 2) * CLS + e], WvS[e * 64 + L + 32], o1);
        }
        g_z[(size_t)tok * 64 + L]      = o0;
        g_z[(size_t)tok * 64 + L + 32] = o1;
        __syncwarp();   // protect uS/rwS before next iteration overwrites
    }
}

// ---------------------------------------------------------------------------
// Kernel B: LN1 -> MLP (gelu exact) -> LN2 -> + shortcut(x@Ws+bs)
// smem: Wm1 16384 | Wm2 16384 | Ws 4096 | bm1 256 | bm2 64 | bs 64 |
//       g1 64 | be1 64 | g2 64 | be2 64   = 37504 floats = 150016 B
// ---------------------------------------------------------------------------
__global__ __launch_bounds__(THREADS, 1)
void mlp_kernel(const float* __restrict__ x,
                const float* __restrict__ g1, const float* __restrict__ be1,
                const float* __restrict__ Wm1, const float* __restrict__ bm1,
                const float* __restrict__ Wm2, const float* __restrict__ bm2,
                const float* __restrict__ g2, const float* __restrict__ be2,
                const float* __restrict__ Ws, const float* __restrict__ bs,
                float* __restrict__ out)
{
    extern __shared__ float sm[];
    float* W1S  = sm;            // [e][d] 64x256
    float* W2S  = sm + 16384;    // [e][d] 256x64
    float* WsS  = sm + 32768;    // [e][d] 64x64
    float* bm1S = sm + 36864;
    float* bm2S = sm + 37120;
    float* bsS  = sm + 37184;
    float* g1S  = sm + 37248;
    float* be1S = sm + 37312;
    float* g2S  = sm + 37376;
    float* be2S = sm + 37440;

    const int tid = threadIdx.x;
    const int wid = tid >> 5;
    const int L   = tid & 31;

    for (int i = tid; i < 16384; i += THREADS) { W1S[i] = Wm1[i]; W2S[i] = Wm2[i]; }
    for (int i = tid; i < 4096;  i += THREADS) WsS[i] = Ws[i];
    if (tid < 256) bm1S[tid] = bm1[tid];
    if (tid < 64) {
        bm2S[tid] = bm2[tid]; bsS[tid] = bs[tid];
        g1S[tid] = g1[tid];   be1S[tid] = be1[tid];
        g2S[tid] = g2[tid];   be2S[tid] = be2[tid];
    }
    __syncthreads();

    for (int tok = blockIdx.x * WARPS + wid; tok < NTOK; tok += STRIDE) {
        const size_t base = (size_t)tok * 64;
        float z0 = g_z[base + L], z1 = g_z[base + L + 32];

        // LN1 (channels L, L+32)
        float mean = warpSum(z0 + z1) * (1.f / 64.f);
        float d0 = z0 - mean, d1 = z1 - mean;
        float var = warpSum(d0 * d0 + d1 * d1) * (1.f / 64.f);
        float inv = rsqrtf(var + 1e-5f);
        float zn0 = d0 * inv * g1S[L]      + be1S[L];
        float zn1 = d1 * inv * g1S[L + 32] + be1S[L + 32];

        // h = zn @ Wm1 + bm1 ; lane owns d = 4L..4L+3 and 128+4L..128+4L+3
        float h[8];
        {
            float4 bA = *(const float4*)(bm1S + 4 * L);
            float4 bB = *(const float4*)(bm1S + 128 + 4 * L);
            h[0]=bA.x; h[1]=bA.y; h[2]=bA.z; h[3]=bA.w;
            h[4]=bB.x; h[5]=bB.y; h[6]=bB.z; h[7]=bB.w;
        }
        #pragma unroll 8
        for (int e = 0; e < 32; e++) {
            float zb = __shfl_sync(0xffffffffu, zn0, e);
            float4 wA = *(const float4*)(W1S + e * 256 + 4 * L);
            float4 wB = *(const float4*)(W1S + e * 256 + 128 + 4 * L);
            h[0]=fmaf(zb,wA.x,h[0]); h[1]=fmaf(zb,wA.y,h[1]);
            h[2]=fmaf(zb,wA.z,h[2]); h[3]=fmaf(zb,wA.w,h[3]);
            h[4]=fmaf(zb,wB.x,h[4]); h[5]=fmaf(zb,wB.y,h[5]);
            h[6]=fmaf(zb,wB.z,h[6]); h[7]=fmaf(zb,wB.w,h[7]);
        }
        #pragma unroll 8
        for (int e = 0; e < 32; e++) {
            float zb = __shfl_sync(0xffffffffu, zn1, e);
            float4 wA = *(const float4*)(W1S + (e + 32) * 256 + 4 * L);
            float4 wB = *(const float4*)(W1S + (e + 32) * 256 + 128 + 4 * L);
            h[0]=fmaf(zb,wA.x,h[0]); h[1]=fmaf(zb,wA.y,h[1]);
            h[2]=fmaf(zb,wA.z,h[2]); h[3]=fmaf(zb,wA.w,h[3]);
            h[4]=fmaf(zb,wB.x,h[4]); h[5]=fmaf(zb,wB.y,h[5]);
            h[6]=fmaf(zb,wB.z,h[6]); h[7]=fmaf(zb,wB.w,h[7]);
        }

        // exact gelu
        #pragma unroll
        for (int j = 0; j < 8; j++)
            h[j] = 0.5f * h[j] * (1.f + erff(h[j] * 0.70710678118654752f));

        // o = h @ Wm2 + bm2 ; lane owns d = 2L, 2L+1
        float o0 = bm2S[2 * L], o1 = bm2S[2 * L + 1];
        #pragma unroll 8
        for (int sl = 0; sl < 32; sl++) {
            #pragma unroll
            for (int j = 0; j < 4; j++) {
                float hb = __shfl_sync(0xffffffffu, h[j], sl);
                int e = sl * 4 + j;
                float2 w2 = *(const float2*)(W2S + e * 64 + 2 * L);
                o0 = fmaf(hb, w2.x, o0); o1 = fmaf(hb, w2.y, o1);
            }
        }
        #pragma unroll 8
        for (int sl = 0; sl < 32; sl++) {
            #pragma unroll
            for (int j = 0; j < 4; j++) {
                float hb = __shfl_sync(0xffffffffu, h[4 + j], sl);
                int e = 128 + sl * 4 + j;
                float2 w2 = *(const float2*)(W2S + e * 64 + 2 * L);
                o0 = fmaf(hb, w2.x, o0); o1 = fmaf(hb, w2.y, o1);
            }
        }

        // LN2 (channels 2L, 2L+1)
        float m2 = warpSum(o0 + o1) * (1.f / 64.f);
        float e0 = o0 - m2, e1 = o1 - m2;
        float v2 = warpSum(e0 * e0 + e1 * e1) * (1.f / 64.f);
        float inv2 = rsqrtf(v2 + 1e-5f);
        float on0 = e0 * inv2 * g2S[2 * L]     + be2S[2 * L];
        float on1 = e1 * inv2 * g2S[2 * L + 1] + be2S[2 * L + 1];

        // shortcut = x @ Ws + bs
        float xa = x[base + 2 * L], xb = x[base + 2 * L + 1];
        float sc0 = bsS[2 * L], sc1 = bsS[2 * L + 1];
        #pragma unroll 8
        for (int sl = 0; sl < 32; sl++) {
            float x0b = __shfl_sync(0xffffffffu, xa, sl);
            float x1b = __shfl_sync(0xffffffffu, xb, sl);
            int e = sl * 2;
            float2 wa = *(const float2*)(WsS + e * 64 + 2 * L);
            float2 wb = *(const float2*)(WsS + (e + 1) * 64 + 2 * L);
            sc0 = fmaf(x0b, wa.x, sc0); sc1 = fmaf(x0b, wa.y, sc1);
            sc0 = fmaf(x1b, wb.x, sc0); sc1 = fmaf(x1b, wb.y, sc1);
        }

        out[base + 2 * L]     = on0 + sc0;
        out[base + 2 * L + 1] = on1 + sc1;
    }
}

// ---------------------------------------------------------------------------
extern "C" void kernel_launch(void* const* d_in, const int* in_sizes, int n_in,
                              void* d_out, int out_size)
{
    const float* u   = (const float*)d_in[0];
    const float* x   = (const float*)d_in[1];
    const float* Wk  = (const float*)d_in[2];
    const float* bk  = (const float*)d_in[3];
    const float* Wq  = (const float*)d_in[4];
    const float* bq  = (const float*)d_in[5];
    const float* Wv  = (const float*)d_in[6];
    const float* bv  = (const float*)d_in[7];
    const float* g1  = (const float*)d_in[8];
    const float* be1 = (const float*)d_in[9];
    const float* Wm1 = (const float*)d_in[10];
    const float* bm1 = (const float*)d_in[11];
    const float* Wm2 = (const float*)d_in[12];
    const float* bm2 = (const float*)d_in[13];
    const float* g2  = (const float*)d_in[14];
    const float* be2 = (const float*)d_in[15];
    const float* Ws  = (const float*)d_in[16];
    const float* bs  = (const float*)d_in[17];
    float* out = (float*)d_out;

    const int smemA = 36288 * 4;   // 145152 B
    const int smemB = 37504 * 4;   // 150016 B
    cudaFuncSetAttribute(attn_kernel, cudaFuncAttributeMaxDynamicSharedMemorySize, smemA);
    cudaFuncSetAttribute(mlp_kernel,  cudaFuncAttributeMaxDynamicSharedMemorySize, smemB);

    attn_kernel<<<GRID, THREADS, smemA>>>(u, x, Wk, bk, Wq, bq, Wv, bv);
    mlp_kernel<<<GRID, THREADS, smemB>>>(x, g1, be1, Wm1, bm1, Wm2, bm2,
                                         g2, be2, Ws, bs, out);
}

// round 6
// speedup vs baseline: 1.7983x; 1.7983x over previous
#include <cuda_runtime.h>
#include <math.h>

// Problem constants
#define BB 8
#define NN 7168
#define NTOK (BB*NN)            // 57344
#define UU 49152
#define GRID 148

__device__ float g_z[(size_t)NTOK * 64];   // attention output scratch (pre-LN)

__device__ __forceinline__ float warpSum(float v) {
    v += __shfl_xor_sync(0xffffffffu, v, 16);
    v += __shfl_xor_sync(0xffffffffu, v, 8);
    v += __shfl_xor_sync(0xffffffffu, v, 4);
    v += __shfl_xor_sync(0xffffffffu, v, 2);
    v += __shfl_xor_sync(0xffffffffu, v, 1);
    return v;
}

// ===========================================================================
// Kernel A: bunched grouped cross-attention -> g_z.  Token-PAIR per warp.
// smem (floats):
//   WqS 4096 | WkTS 4096 | WvS 4096 | bqS 64 | bkS 64 | bvS 64   (=12480)
//   per warp (12): uS 32*68=2176 | rwS 2*4*68=544 | qS 128 | xT 128 |
//                  lgS 128 | atS 128   (=3232)
// total = 12480 + 12*3232 = 51264 floats = 205056 B
// ===========================================================================
#define ATHREADS 384
#define AWARPS 12

__global__ __launch_bounds__(ATHREADS, 1)
void attn_kernel(const float* __restrict__ u, const float* __restrict__ x,
                 const float* __restrict__ Wk, const float* __restrict__ bk,
                 const float* __restrict__ Wq, const float* __restrict__ bq,
                 const float* __restrict__ Wv, const float* __restrict__ bv)
{
    extern __shared__ float sm[];
    float* WqS  = sm;
    float* WkTS = sm + 4096;
    float* WvS  = sm + 8192;
    float* bqS  = sm + 12288;
    float* bkS  = sm + 12352;
    float* bvS  = sm + 12416;

    const int tid = threadIdx.x;
    const int wid = tid >> 5;
    const int L   = tid & 31;

    float* warpS = sm + 12480 + wid * 3232;
    float* uS  = warpS;          // 32 x 68
    float* rwS = warpS + 2176;   // 2 tokens x 4 x 68 (r, later w)
    float* qS  = warpS + 2720;   // [ch][tok] 64 x 2
    float* xT  = warpS + 2848;   // [ch][tok] 64 x 2
    float* lgS = warpS + 2976;   // 128 logits
    float* atS = warpS + 3104;   // 128 attn

    for (int i = tid; i < 4096; i += ATHREADS) {
        WqS[i] = Wq[i];
        WvS[i] = Wv[i];
        WkTS[(i & 63) * 64 + (i >> 6)] = Wk[i];   // transpose Wk -> [d][e]
    }
    if (tid < 64) { bqS[tid] = bq[tid]; bkS[tid] = bk[tid]; bvS[tid] = bv[tid]; }
    __syncthreads();

    const int NPAIR = NTOK / 2;
    for (int pair = blockIdx.x * AWARPS + wid; pair < NPAIR; pair += GRID * AWARPS) {
        const int tok0 = pair * 2;
        const int b = tok0 / NN;
        const int n = tok0 - b * NN;          // even

        int to, urow;
        if (n < 4096) {                       // bunch 0: rel=2, to=4
            to = 4;
            urow = (n < 2048) ? (n * 4) : (24576 + (n - 2048) * 4);
        } else if (n < 6144) {                // bunch 1: rel=4, to=8
            int m = n - 4096;
            to = 8;
            urow = (m < 1024) ? (8192 + m * 8) : (32768 + (m - 1024) * 8);
        } else {                              // bunch 2: rel=8, to=16
            int m = n - 6144;
            to = 16;
            urow = (m < 512) ? (16384 + m * 16) : (40960 + (m - 512) * 16);
        }
        // token n+1 uses rows [urow+to, urow+2*to) -> contiguous 2*to rows

        const float* xr = x + (size_t)tok0 * 64;
        const float4* ur4 = (const float4*)(u + ((size_t)b * UU + (size_t)urow) * 64);

        // stage u tile: 2*to rows of 64 floats, padded stride 68
        const int cnt4 = 2 * to * 16;
        #pragma unroll 4
        for (int i4 = L; i4 < cnt4; i4 += 32) {
            float4 v = ur4[i4];
            *((float4*)(uS + (i4 >> 4) * 68) + (i4 & 15)) = v;
        }

        // stage x transposed: xT[ch][tok]
        {
            float2 xa = *(const float2*)(xr + 2 * L);
            float2 xb = *(const float2*)(xr + 64 + 2 * L);
            float4 st = make_float4(xa.x, xb.x, xa.y, xb.y);
            *(float4*)(xT + 4 * L) = st;
        }
        __syncwarp();

        // q = x @ Wq + bq for both tokens; lane owns ch 2L, 2L+1
        float qa0 = bqS[2 * L], qa1 = bqS[2 * L + 1];
        float qb0 = qa0,        qb1 = qa1;
        #pragma unroll 8
        for (int e = 0; e < 64; e++) {
            float2 xe = *(const float2*)(xT + 2 * e);        // (x0[e], x1[e]) bcast
            float2 w  = *(const float2*)(WqS + e * 64 + 2 * L);
            qa0 = fmaf(xe.x, w.x, qa0); qa1 = fmaf(xe.x, w.y, qa1);
            qb0 = fmaf(xe.y, w.x, qb0); qb1 = fmaf(xe.y, w.y, qb1);
        }
        *(float4*)(qS + 4 * L) = make_float4(qa0, qb0, qa1, qb1);  // qS[ch][tok]
        __syncwarp();

        // r[t][g][e] (e = L, L+32) and s[t][g]
        float s0_0, s0_1, s0_2, s0_3, s1_0, s1_1, s1_2, s1_3;
        #pragma unroll
        for (int g = 0; g < 4; g++) {
            float ra0 = 0.f, ra1 = 0.f, rb0 = 0.f, rb1 = 0.f, sa = 0.f, sb = 0.f;
            #pragma unroll
            for (int dd = 0; dd < 16; dd++) {
                const int d = g * 16 + dd;
                float2 qd = *(const float2*)(qS + 2 * d);    // (q0[d], q1[d]) bcast
                float wkl = WkTS[d * 64 + L];
                float wkh = WkTS[d * 64 + L + 32];
                float bkd = bkS[d];
                ra0 = fmaf(wkl, qd.x, ra0); ra1 = fmaf(wkh, qd.x, ra1);
                rb0 = fmaf(wkl, qd.y, rb0); rb1 = fmaf(wkh, qd.y, rb1);
                sa  = fmaf(bkd, qd.x, sa);  sb  = fmaf(bkd, qd.y, sb);
            }
            rwS[g * 68 + L]            = ra0;
            rwS[g * 68 + L + 32]       = ra1;
            rwS[272 + g * 68 + L]      = rb0;
            rwS[272 + g * 68 + L + 32] = rb1;
            if (g == 0) { s0_0 = sa; s1_0 = sb; }
            else if (g == 1) { s0_1 = sa; s1_1 = sb; }
            else if (g == 2) { s0_2 = sa; s1_2 = sb; }
            else { s0_3 = sa; s1_3 = sb; }
        }
        __syncwarp();

        // logits[p]: p = t2*4+g, t2 in [0, 2*to)
        const int P = to * 8;
        #pragma unroll
        for (int rep = 0; rep < 4; rep++) {
            int p = rep * 32 + L;
            if (p < P) {
                int t2 = p >> 2, g = p & 3;
                int tk = (t2 >= to);
                float acc = tk ? ((g == 0) ? s1_0 : (g == 1) ? s1_1 : (g == 2) ? s1_2 : s1_3)
                               : ((g == 0) ? s0_0 : (g == 1) ? s0_1 : (g == 2) ? s0_2 : s0_3);
                const float4* up = (const float4*)(uS + t2 * 68);
                const float4* rp = (const float4*)(rwS + tk * 272 + g * 68);
                #pragma unroll
                for (int e4 = 0; e4 < 16; e4++) {
                    float4 a = up[e4], bb = rp[e4];
                    acc = fmaf(a.x, bb.x, acc);
                    acc = fmaf(a.y, bb.y, acc);
                    acc = fmaf(a.z, bb.z, acc);
                    acc = fmaf(a.w, bb.w, acc);
                }
                lgS[p] = acc * 0.125f;
            }
        }
        __syncwarp();

        // softmax over t, per (token, group): 8 lanes
        if (L < 8) {
            int tk = L >> 2, g = L & 3;
            int base = tk * to;
            float mx = -1e30f;
            for (int t = 0; t < to; t++) mx = fmaxf(mx, lgS[(base + t) * 4 + g]);
            float ss = 0.f;
            for (int t = 0; t < to; t++) {
                float e = expf(lgS[(base + t) * 4 + g] - mx);
                atS[(base + t) * 4 + g] = e;
                ss += e;
            }
            float is = 1.f / ss;
            for (int t = 0; t < to; t++) atS[(base + t) * 4 + g] *= is;
        }
        __syncwarp();

        // w[t][g][e] = sum_t attn * u ; e = L, L+32
        float wa0[4] = {0.f,0.f,0.f,0.f}, wa1[4] = {0.f,0.f,0.f,0.f};
        float wb0[4] = {0.f,0.f,0.f,0.f}, wb1[4] = {0.f,0.f,0.f,0.f};
        #pragma unroll 4
        for (int t = 0; t < to; t++) {
            float4 a0 = *(const float4*)(atS + t * 4);
            float4 a1 = *(const float4*)(atS + (to + t) * 4);
            float u00 = uS[t * 68 + L],        u01 = uS[t * 68 + L + 32];
            float u10 = uS[(to + t) * 68 + L], u11 = uS[(to + t) * 68 + L + 32];
            wa0[0] = fmaf(a0.x, u00, wa0[0]); wa1[0] = fmaf(a0.x, u01, wa1[0]);
            wa0[1] = fmaf(a0.y, u00, wa0[1]); wa1[1] = fmaf(a0.y, u01, wa1[1]);
            wa0[2] = fmaf(a0.z, u00, wa0[2]); wa1[2] = fmaf(a0.z, u01, wa1[2]);
            wa0[3] = fmaf(a0.w, u00, wa0[3]); wa1[3] = fmaf(a0.w, u01, wa1[3]);
            wb0[0] = fmaf(a1.x, u10, wb0[0]); wb1[0] = fmaf(a1.x, u11, wb1[0]);
            wb0[1] = fmaf(a1.y, u10, wb0[1]); wb1[1] = fmaf(a1.y, u11, wb1[1]);
            wb0[2] = fmaf(a1.z, u10, wb0[2]); wb1[2] = fmaf(a1.z, u11, wb1[2]);
            wb0[3] = fmaf(a1.w, u10, wb0[3]); wb1[3] = fmaf(a1.w, u11, wb1[3]);
        }
        __syncwarp();   // logits reads of rwS done; safe to overwrite with w
        #pragma unroll
        for (int g = 0; g < 4; g++) {
            rwS[g * 68 + L]            = wa0[g];
            rwS[g * 68 + L + 32]       = wa1[g];
            rwS[272 + g * 68 + L]      = wb0[g];
            rwS[272 + g * 68 + L + 32] = wb1[g];
        }
        __syncwarp();

        // out[c] = w[g(c)] . Wv[:,c] + bv[c] ; lane owns ch 2L, 2L+1 (same group)
        {
            const int g = L >> 3;     // group of channel 2L (= (2L)>>4)
            const float* w0 = rwS + g * 68;
            const float* w1 = rwS + 272 + g * 68;
            float oa0 = bvS[2 * L], oa1 = bvS[2 * L + 1];
            float ob0 = oa0,        ob1 = oa1;
            #pragma unroll 8
            for (int e = 0; e < 64; e++) {
                float2 wv = *(const float2*)(WvS + e * 64 + 2 * L);
                float we0 = w0[e], we1 = w1[e];
                oa0 = fmaf(we0, wv.x, oa0); oa1 = fmaf(we0, wv.y, oa1);
                ob0 = fmaf(we1, wv.x, ob0); ob1 = fmaf(we1, wv.y, ob1);
            }
            *(float2*)(g_z + (size_t)tok0 * 64 + 2 * L)       = make_float2(oa0, oa1);
            *(float2*)(g_z + (size_t)(tok0 + 1) * 64 + 2 * L) = make_float2(ob0, ob1);
        }
        __syncwarp();   // protect per-warp tiles before next iteration
    }
}

// ===========================================================================
// Kernel B: LN1 -> MLP (exact gelu) -> LN2 -> + shortcut(x@Ws+bs)
// 4 tokens per warp.  Activation tiles in [ch][tok] layout for float4 bcast.
// 384 threads (12 warps) so the 65536-reg RF gives 170 regs/thread (no spills).
// smem: W1S 16384 | W2S 16384 | WsS 4096 | bm1S 256 | small vecs 384
//       per warp (12): znT 256 | xT 256 | hT 512 (swizzled)
// total = 37504 + 12*1024 = 49792 floats = 199168 B
// ===========================================================================
#define MTHREADS 384
#define MWARPS 12

__device__ __forceinline__ int hswz(int e) {   // conflict-free slot for hT
    return (e ^ ((e >> 3) & 3)) * 4;
}

__global__ __launch_bounds__(MTHREADS, 1)
void mlp_kernel(const float* __restrict__ x,
                const float* __restrict__ g1, const float* __restrict__ be1,
                const float* __restrict__ Wm1, const float* __restrict__ bm1,
                const float* __restrict__ Wm2, const float* __restrict__ bm2,
                const float* __restrict__ g2, const float* __restrict__ be2,
                const float* __restrict__ Ws, const float* __restrict__ bs,
                float* __restrict__ out)
{
    extern __shared__ float sm[];
    float* W1S  = sm;            // [e][256]
    float* W2S  = sm + 16384;    // [e][64]
    float* WsS  = sm + 32768;    // [e][64]
    float* bm1S = sm + 36864;
    float* bm2S = sm + 37120;
    float* bsS  = sm + 37184;
    float* g1S  = sm + 37248;
    float* be1S = sm + 37312;
    float* g2S  = sm + 37376;
    float* be2S = sm + 37440;

    const int tid = threadIdx.x;
    const int wid = tid >> 5;
    const int L   = tid & 31;

    float* wbase = sm + 37504 + wid * 1024;
    float* znT = wbase;          // [ch][4]
    float* xT  = wbase + 256;    // [ch][4]
    float* hT  = wbase + 512;    // 128 x 4, swizzled

    for (int i = tid; i < 16384; i += MTHREADS) { W1S[i] = Wm1[i]; W2S[i] = Wm2[i]; }
    for (int i = tid; i < 4096;  i += MTHREADS) WsS[i] = Ws[i];
    if (tid < 256) bm1S[tid] = bm1[tid];
    if (tid < 64) {
        bm2S[tid] = bm2[tid]; bsS[tid] = bs[tid];
        g1S[tid] = g1[tid];   be1S[tid] = be1[tid];
        g2S[tid] = g2[tid];   be2S[tid] = be2[tid];
    }
    __syncthreads();

    const int NGRP = NTOK / 4;
    for (int grp = blockIdx.x * MWARPS + wid; grp < NGRP; grp += GRID * MWARPS) {
        const int tok0 = grp * 4;
        const size_t base = (size_t)tok0 * 64;

        // ---- LN1 on 4 tokens (lane owns ch L, L+32) ----
        float zn0[4], zn1[4];
        #pragma unroll
        for (int t = 0; t < 4; t++) {
            float z0 = g_z[base + t * 64 + L];
            float z1 = g_z[base + t * 64 + L + 32];
            float mean = warpSum(z0 + z1) * (1.f / 64.f);
            float d0 = z0 - mean, d1 = z1 - mean;
            float var = warpSum(d0 * d0 + d1 * d1) * (1.f / 64.f);
            float inv = rsqrtf(var + 1e-5f);
            zn0[t] = d0 * inv * g1S[L]      + be1S[L];
            zn1[t] = d1 * inv * g1S[L + 32] + be1S[L + 32];
        }
        *(float4*)(znT + 4 * L)        = make_float4(zn0[0], zn0[1], zn0[2], zn0[3]);
        *(float4*)(znT + 4 * (L + 32)) = make_float4(zn1[0], zn1[1], zn1[2], zn1[3]);

        // stage x transposed for the shortcut
        {
            float xa[4], xb[4];
            #pragma unroll
            for (int t = 0; t < 4; t++) {
                xa[t] = x[base + t * 64 + L];
                xb[t] = x[base + t * 64 + L + 32];
            }
            *(float4*)(xT + 4 * L)        = make_float4(xa[0], xa[1], xa[2], xa[3]);
            *(float4*)(xT + 4 * (L + 32)) = make_float4(xb[0], xb[1], xb[2], xb[3]);
        }
        __syncwarp();

        // ---- h = zn @ Wm1 + bm1 ; lane owns d = 4L..4L+3 and 128+4L..+3 ----
        float h0[8], h1[8], h2[8], h3[8];
        {
            float4 bA = *(const float4*)(bm1S + 4 * L);
            float4 bB = *(const float4*)(bm1S + 128 + 4 * L);
            h0[0]=bA.x; h0[1]=bA.y; h0[2]=bA.z; h0[3]=bA.w;
            h0[4]=bB.x; h0[5]=bB.y; h0[6]=bB.z; h0[7]=bB.w;
            #pragma unroll
            for (int j = 0; j < 8; j++) { h1[j]=h0[j]; h2[j]=h0[j]; h3[j]=h0[j]; }
        }
        #pragma unroll 4
        for (int e = 0; e < 64; e++) {
            float4 zn4 = *(const float4*)(znT + 4 * e);      // 4 tokens, bcast
            float4 wA = *(const float4*)(W1S + e * 256 + 4 * L);
            float4 wB = *(const float4*)(W1S + e * 256 + 128 + 4 * L);
            h0[0]=fmaf(zn4.x,wA.x,h0[0]); h0[1]=fmaf(zn4.x,wA.y,h0[1]);
            h0[2]=fmaf(zn4.x,wA.z,h0[2]); h0[3]=fmaf(zn4.x,wA.w,h0[3]);
            h0[4]=fmaf(zn4.x,wB.x,h0[4]); h0[5]=fmaf(zn4.x,wB.y,h0[5]);
            h0[6]=fmaf(zn4.x,wB.z,h0[6]); h0[7]=fmaf(zn4.x,wB.w,h0[7]);
            h1[0]=fmaf(zn4.y,wA.x,h1[0]); h1[1]=fmaf(zn4.y,wA.y,h1[1]);
            h1[2]=fmaf(zn4.y,wA.z,h1[2]); h1[3]=fmaf(zn4.y,wA.w,h1[3]);
            h1[4]=fmaf(zn4.y,wB.x,h1[4]); h1[5]=fmaf(zn4.y,wB.y,h1[5]);
            h1[6]=fmaf(zn4.y,wB.z,h1[6]); h1[7]=fmaf(zn4.y,wB.w,h1[7]);
            h2[0]=fmaf(zn4.z,wA.x,h2[0]); h2[1]=fmaf(zn4.z,wA.y,h2[1]);
            h2[2]=fmaf(zn4.z,wA.z,h2[2]); h2[3]=fmaf(zn4.z,wA.w,h2[3]);
            h2[4]=fmaf(zn4.z,wB.x,h2[4]); h2[5]=fmaf(zn4.z,wB.y,h2[5]);
            h2[6]=fmaf(zn4.z,wB.z,h2[6]); h2[7]=fmaf(zn4.z,wB.w,h2[7]);
            h3[0]=fmaf(zn4.w,wA.x,h3[0]); h3[1]=fmaf(zn4.w,wA.y,h3[1]);
            h3[2]=fmaf(zn4.w,wA.z,h3[2]); h3[3]=fmaf(zn4.w,wA.w,h3[3]);
            h3[4]=fmaf(zn4.w,wB.x,h3[4]); h3[5]=fmaf(zn4.w,wB.y,h3[5]);
            h3[6]=fmaf(zn4.w,wB.z,h3[6]); h3[7]=fmaf(zn4.w,wB.w,h3[7]);
        }

        // exact gelu
        #pragma unroll
        for (int j = 0; j < 8; j++) {
            h0[j] = 0.5f * h0[j] * (1.f + erff(h0[j] * 0.70710678118654752f));
            h1[j] = 0.5f * h1[j] * (1.f + erff(h1[j] * 0.70710678118654752f));
            h2[j] = 0.5f * h2[j] * (1.f + erff(h2[j] * 0.70710678118654752f));
            h3[j] = 0.5f * h3[j] * (1.f + erff(h3[j] * 0.70710678118654752f));
        }

        // ---- o = h @ Wm2 + bm2 in two e-halves; lane owns ch 2L, 2L+1 ----
        float o0[4], o1[4];
        {
            float2 b2 = *(const float2*)(bm2S + 2 * L);
            #pragma unroll
            for (int t = 0; t < 4; t++) { o0[t] = b2.x; o1[t] = b2.y; }
        }
        // half 0: channels e in [0,128)
        #pragma unroll
        for (int j = 0; j < 4; j++)
            *(float4*)(hT + hswz(4 * L + j)) = make_float4(h0[j], h1[j], h2[j], h3[j]);
        __syncwarp();
        #pragma unroll 4
        for (int e = 0; e < 128; e++) {
            float4 hv = *(const float4*)(hT + hswz(e));
            float2 w2 = *(const float2*)(W2S + e * 64 + 2 * L);
            o0[0]=fmaf(hv.x,w2.x,o0[0]); o1[0]=fmaf(hv.x,w2.y,o1[0]);
            o0[1]=fmaf(hv.y,w2.x,o0[1]); o1[1]=fmaf(hv.y,w2.y,o1[1]);
            o0[2]=fmaf(hv.z,w2.x,o0[2]); o1[2]=fmaf(hv.z,w2.y,o1[2]);
            o0[3]=fmaf(hv.w,w2.x,o0[3]); o1[3]=fmaf(hv.w,w2.y,o1[3]);
        }
        __syncwarp();
        // half 1: channels e in [128,256)
        #pragma unroll
        for (int j = 0; j < 4; j++)
            *(float4*)(hT + hswz(4 * L + j)) = make_float4(h0[4+j], h1[4+j], h2[4+j], h3[4+j]);
        __syncwarp();
        #pragma unroll 4
        for (int e = 0; e < 128; e++) {
            float4 hv = *(const float4*)(hT + hswz(e));
            float2 w2 = *(const float2*)(W2S + (e + 128) * 64 + 2 * L);
            o0[0]=fmaf(hv.x,w2.x,o0[0]); o1[0]=fmaf(hv.x,w2.y,o1[0]);
            o0[1]=fmaf(hv.y,w2.x,o0[1]); o1[1]=fmaf(hv.y,w2.y,o1[1]);
            o0[2]=fmaf(hv.z,w2.x,o0[2]); o1[2]=fmaf(hv.z,w2.y,o1[2]);
            o0[3]=fmaf(hv.w,w2.x,o0[3]); o1[3]=fmaf(hv.w,w2.y,o1[3]);
        }

        // ---- shortcut = x @ Ws + bs ----
        float sc0[4], sc1[4];
        {
            float2 b2 = *(const float2*)(bsS + 2 * L);
            #pragma unroll
            for (int t = 0; t < 4; t++) { sc0[t] = b2.x; sc1[t] = b2.y; }
        }
        #pragma unroll 4
        for (int e = 0; e < 64; e++) {
            float4 xe = *(const float4*)(xT + 4 * e);
            float2 ws = *(const float2*)(WsS + e * 64 + 2 * L);
            sc0[0]=fmaf(xe.x,ws.x,sc0[0]); sc1[0]=fmaf(xe.x,ws.y,sc1[0]);
            sc0[1]=fmaf(xe.y,ws.x,sc0[1]); sc1[1]=fmaf(xe.y,ws.y,sc1[1]);
            sc0[2]=fmaf(xe.z,ws.x,sc0[2]); sc1[2]=fmaf(xe.z,ws.y,sc1[2]);
            sc0[3]=fmaf(xe.w,ws.x,sc0[3]); sc1[3]=fmaf(xe.w,ws.y,sc1[3]);
        }

        // ---- LN2 + add shortcut, store ----
        #pragma unroll
        for (int t = 0; t < 4; t++) {
            float m2 = warpSum(o0[t] + o1[t]) * (1.f / 64.f);
            float e0 = o0[t] - m2, e1 = o1[t] - m2;
            float v2 = warpSum(e0 * e0 + e1 * e1) * (1.f / 64.f);
            float inv2 = rsqrtf(v2 + 1e-5f);
            float on0 = e0 * inv2 * g2S[2 * L]     + be2S[2 * L];
            float on1 = e1 * inv2 * g2S[2 * L + 1] + be2S[2 * L + 1];
            *(float2*)(out + base + t * 64 + 2 * L) = make_float2(on0 + sc0[t], on1 + sc1[t]);
        }
        __syncwarp();   // protect tiles before next group
    }
}

// ===========================================================================
extern "C" void kernel_launch(void* const* d_in, const int* in_sizes, int n_in,
                              void* d_out, int out_size)
{
    const float* u   = (const float*)d_in[0];
    const float* x   = (const float*)d_in[1];
    const float* Wk  = (const float*)d_in[2];
    const float* bk  = (const float*)d_in[3];
    const float* Wq  = (const float*)d_in[4];
    const float* bq  = (const float*)d_in[5];
    const float* Wv  = (const float*)d_in[6];
    const float* bv  = (const float*)d_in[7];
    const float* g1  = (const float*)d_in[8];
    const float* be1 = (const float*)d_in[9];
    const float* Wm1 = (const float*)d_in[10];
    const float* bm1 = (const float*)d_in[11];
    const float* Wm2 = (const float*)d_in[12];
    const float* bm2 = (const float*)d_in[13];
    const float* g2  = (const float*)d_in[14];
    const float* be2 = (const float*)d_in[15];
    const float* Ws  = (const float*)d_in[16];
    const float* bs  = (const float*)d_in[17];
    float* out = (float*)d_out;

    const int smemA = 51264 * 4;   // 205056 B
    const int smemB = 49792 * 4;   // 199168 B
    cudaFuncSetAttribute(attn_kernel, cudaFuncAttributeMaxDynamicSharedMemorySize, smemA);
    cudaFuncSetAttribute(mlp_kernel,  cudaFuncAttributeMaxDynamicSharedMemorySize, smemB);

    attn_kernel<<<GRID, ATHREADS, smemA>>>(u, x, Wk, bk, Wq, bq, Wv, bv);
    mlp_kernel<<<GRID, MTHREADS, smemB>>>(x, g1, be1, Wm1, bm1, Wm2, bm2,
                                          g2, be2, Ws, bs, out);
}

// round 12
// speedup vs baseline: 1.8447x; 1.0258x over previous
#include <cuda_runtime.h>
#include <math.h>

// Problem constants
#define BB 8
#define NN 7168
#define NTOK (BB*NN)            // 57344
#define UU 49152
#define GRID 148

__device__ float g_z[(size_t)NTOK * 64];   // attention output scratch (pre-LN)

__device__ __forceinline__ float warpSum(float v) {
    v += __shfl_xor_sync(0xffffffffu, v, 16);
    v += __shfl_xor_sync(0xffffffffu, v, 8);
    v += __shfl_xor_sync(0xffffffffu, v, 4);
    v += __shfl_xor_sync(0xffffffffu, v, 2);
    v += __shfl_xor_sync(0xffffffffu, v, 1);
    return v;
}

// ===========================================================================
// Kernel A: bunched grouped cross-attention -> g_z.  Token-PAIR per warp.
// In-register butterfly softmax (no lgS, no 8-lane serial block).
// smem (floats):
//   WqS 4096 | WkTS 4096 | WvS 4096 | bqS 64 | bkS 64 | bvS 64   (=12480)
//   per warp (14): uS 32*68=2176 | rwS 544 | qS 128 | xT 128 | atS 128 (=3104)
// total = 12480 + 14*3104 = 55936 floats = 223744 B
// ===========================================================================
#define ATHREADS 448
#define AWARPS 14

__global__ __launch_bounds__(ATHREADS, 1)
void attn_kernel(const float* __restrict__ u, const float* __restrict__ x,
                 const float* __restrict__ Wk, const float* __restrict__ bk,
                 const float* __restrict__ Wq, const float* __restrict__ bq,
                 const float* __restrict__ Wv, const float* __restrict__ bv)
{
    extern __shared__ float sm[];
    float* WqS  = sm;
    float* WkTS = sm + 4096;
    float* WvS  = sm + 8192;
    float* bqS  = sm + 12288;
    float* bkS  = sm + 12352;
    float* bvS  = sm + 12416;

    const int tid = threadIdx.x;
    const int wid = tid >> 5;
    const int L   = tid & 31;

    float* warpS = sm + 12480 + wid * 3104;
    float* uS  = warpS;          // 32 x 68
    float* rwS = warpS + 2176;   // 2 tokens x 4 x 68 (r, later w)
    float* qS  = warpS + 2720;   // [ch][tok] 64 x 2
    float* xT  = warpS + 2848;   // [ch][tok] 64 x 2
    float* atS = warpS + 2976;   // 128 attn

    for (int i = tid; i < 4096; i += ATHREADS) {
        WqS[i] = Wq[i];
        WvS[i] = Wv[i];
        WkTS[(i & 63) * 64 + (i >> 6)] = Wk[i];   // transpose Wk -> [d][e]
    }
    if (tid < 64) { bqS[tid] = bq[tid]; bkS[tid] = bk[tid]; bvS[tid] = bv[tid]; }
    __syncthreads();

    const int NPAIR = NTOK / 2;
    for (int pair = blockIdx.x * AWARPS + wid; pair < NPAIR; pair += GRID * AWARPS) {
        const int tok0 = pair * 2;
        const int b = tok0 / NN;
        const int n = tok0 - b * NN;          // even

        int to, urow;
        if (n < 4096) {                       // bunch 0: rel=2, to=4
            to = 4;
            urow = (n < 2048) ? (n * 4) : (24576 + (n - 2048) * 4);
        } else if (n < 6144) {                // bunch 1: rel=4, to=8
            int m = n - 4096;
            to = 8;
            urow = (m < 1024) ? (8192 + m * 8) : (32768 + (m - 1024) * 8);
        } else {                              // bunch 2: rel=8, to=16
            int m = n - 6144;
            to = 16;
            urow = (m < 512) ? (16384 + m * 16) : (40960 + (m - 512) * 16);
        }
        // token n+1 uses rows [urow+to, urow+2*to) -> contiguous 2*to rows

        const float* xr = x + (size_t)tok0 * 64;
        const float4* ur4 = (const float4*)(u + ((size_t)b * UU + (size_t)urow) * 64);

        // stage u tile: 2*to rows of 64 floats, padded stride 68
        const int cnt4 = 2 * to * 16;
        #pragma unroll 4
        for (int i4 = L; i4 < cnt4; i4 += 32) {
            float4 v = ur4[i4];
            *((float4*)(uS + (i4 >> 4) * 68) + (i4 & 15)) = v;
        }

        // stage x transposed: xT[ch][tok]
        {
            float2 xa = *(const float2*)(xr + 2 * L);
            float2 xb = *(const float2*)(xr + 64 + 2 * L);
            float4 st = make_float4(xa.x, xb.x, xa.y, xb.y);
            *(float4*)(xT + 4 * L) = st;
        }
        __syncwarp();

        // q = x @ Wq + bq for both tokens; lane owns ch 2L, 2L+1
        float qa0 = bqS[2 * L], qa1 = bqS[2 * L + 1];
        float qb0 = qa0,        qb1 = qa1;
        #pragma unroll 8
        for (int e = 0; e < 64; e++) {
            float2 xe = *(const float2*)(xT + 2 * e);        // (x0[e], x1[e]) bcast
            float2 w  = *(const float2*)(WqS + e * 64 + 2 * L);
            qa0 = fmaf(xe.x, w.x, qa0); qa1 = fmaf(xe.x, w.y, qa1);
            qb0 = fmaf(xe.y, w.x, qb0); qb1 = fmaf(xe.y, w.y, qb1);
        }
        *(float4*)(qS + 4 * L) = make_float4(qa0, qb0, qa1, qb1);  // qS[ch][tok]
        __syncwarp();

        // r[t][g][e] (e = L, L+32) and s[t][g]
        float s0_0, s0_1, s0_2, s0_3, s1_0, s1_1, s1_2, s1_3;
        #pragma unroll
        for (int g = 0; g < 4; g++) {
            float ra0 = 0.f, ra1 = 0.f, rb0 = 0.f, rb1 = 0.f, sa = 0.f, sb = 0.f;
            #pragma unroll
            for (int dd = 0; dd < 16; dd++) {
                const int d = g * 16 + dd;
                float2 qd = *(const float2*)(qS + 2 * d);    // (q0[d], q1[d]) bcast
                float wkl = WkTS[d * 64 + L];
                float wkh = WkTS[d * 64 + L + 32];
                float bkd = bkS[d];
                ra0 = fmaf(wkl, qd.x, ra0); ra1 = fmaf(wkh, qd.x, ra1);
                rb0 = fmaf(wkl, qd.y, rb0); rb1 = fmaf(wkh, qd.y, rb1);
                sa  = fmaf(bkd, qd.x, sa);  sb  = fmaf(bkd, qd.y, sb);
            }
            rwS[g * 68 + L]            = ra0;
            rwS[g * 68 + L + 32]       = ra1;
            rwS[272 + g * 68 + L]      = rb0;
            rwS[272 + g * 68 + L + 32] = rb1;
            if (g == 0) { s0_0 = sa; s1_0 = sb; }
            else if (g == 1) { s0_1 = sa; s1_1 = sb; }
            else if (g == 2) { s0_2 = sa; s1_2 = sb; }
            else { s0_3 = sa; s1_3 = sb; }
        }
        __syncwarp();

        // logits in registers: lg[rep], rep < nrep = to/4; p = rep*32+L = t2*4+g
        const int nrep = to >> 2;
        float lg[4];
        #pragma unroll
        for (int rep = 0; rep < 4; rep++) {
            if (rep < nrep) {
                int p = rep * 32 + L;
                int t2 = p >> 2, g = p & 3;
                int tk = (t2 >= to);
                float acc = tk ? ((g == 0) ? s1_0 : (g == 1) ? s1_1 : (g == 2) ? s1_2 : s1_3)
                               : ((g == 0) ? s0_0 : (g == 1) ? s0_1 : (g == 2) ? s0_2 : s0_3);
                const float4* up = (const float4*)(uS + t2 * 68);
                const float4* rp = (const float4*)(rwS + tk * 272 + g * 68);
                #pragma unroll
                for (int e4 = 0; e4 < 16; e4++) {
                    float4 a = up[e4], bb = rp[e4];
                    acc = fmaf(a.x, bb.x, acc);
                    acc = fmaf(a.y, bb.y, acc);
                    acc = fmaf(a.z, bb.z, acc);
                    acc = fmaf(a.w, bb.w, acc);
                }
                lg[rep] = acc * 0.125f;
            }
        }

        // in-register softmax over t per (token, group), butterfly shfl
        if (to == 4) {
            // rep0 only: lanes 0-15 token0 (t2 0-3), 16-31 token1; strides 4,8
            float m = lg[0];
            m = fmaxf(m, __shfl_xor_sync(0xffffffffu, m, 4));
            m = fmaxf(m, __shfl_xor_sync(0xffffffffu, m, 8));
            float e = expf(lg[0] - m);
            float s = e;
            s += __shfl_xor_sync(0xffffffffu, s, 4);
            s += __shfl_xor_sync(0xffffffffu, s, 8);
            atS[L] = e / s;
        } else if (to == 8) {
            // rep r = token r; strides 4,8,16 within rep
            #pragma unroll
            for (int rep = 0; rep < 2; rep++) {
                float m = lg[rep];
                m = fmaxf(m, __shfl_xor_sync(0xffffffffu, m, 4));
                m = fmaxf(m, __shfl_xor_sync(0xffffffffu, m, 8));
                m = fmaxf(m, __shfl_xor_sync(0xffffffffu, m, 16));
                float e = expf(lg[rep] - m);
                float s = e;
                s += __shfl_xor_sync(0xffffffffu, s, 4);
                s += __shfl_xor_sync(0xffffffffu, s, 8);
                s += __shfl_xor_sync(0xffffffffu, s, 16);
                atS[rep * 32 + L] = e / s;
            }
        } else {
            // to==16: token0 = reps 0,1; token1 = reps 2,3
            #pragma unroll
            for (int half = 0; half < 2; half++) {
                float la = lg[half * 2], lb = lg[half * 2 + 1];
                float m = fmaxf(la, lb);
                m = fmaxf(m, __shfl_xor_sync(0xffffffffu, m, 4));
                m = fmaxf(m, __shfl_xor_sync(0xffffffffu, m, 8));
                m = fmaxf(m, __shfl_xor_sync(0xffffffffu, m, 16));
                float ea = expf(la - m), eb = expf(lb - m);
                float s = ea + eb;
                s += __shfl_xor_sync(0xffffffffu, s, 4);
                s += __shfl_xor_sync(0xffffffffu, s, 8);
                s += __shfl_xor_sync(0xffffffffu, s, 16);
                float is = 1.f / s;
                atS[half * 64 + L]      = ea * is;
                atS[half * 64 + 32 + L] = eb * is;
            }
        }
        __syncwarp();

        // w[t][g][e] = sum_t attn * u ; e = L, L+32
        float wa0[4] = {0.f,0.f,0.f,0.f}, wa1[4] = {0.f,0.f,0.f,0.f};
        float wb0[4] = {0.f,0.f,0.f,0.f}, wb1[4] = {0.f,0.f,0.f,0.f};
        #pragma unroll 4
        for (int t = 0; t < to; t++) {
            float4 a0 = *(const float4*)(atS + t * 4);
            float4 a1 = *(const float4*)(atS + (to + t) * 4);
            float u00 = uS[t * 68 + L],        u01 = uS[t * 68 + L + 32];
            float u10 = uS[(to + t) * 68 + L], u11 = uS[(to + t) * 68 + L + 32];
            wa0[0] = fmaf(a0.x, u00, wa0[0]); wa1[0] = fmaf(a0.x, u01, wa1[0]);
            wa0[1] = fmaf(a0.y, u00, wa0[1]); wa1[1] = fmaf(a0.y, u01, wa1[1]);
            wa0[2] = fmaf(a0.z, u00, wa0[2]); wa1[2] = fmaf(a0.z, u01, wa1[2]);
            wa0[3] = fmaf(a0.w, u00, wa0[3]); wa1[3] = fmaf(a0.w, u01, wa1[3]);
            wb0[0] = fmaf(a1.x, u10, wb0[0]); wb1[0] = fmaf(a1.x, u11, wb1[0]);
            wb0[1] = fmaf(a1.y, u10, wb0[1]); wb1[1] = fmaf(a1.y, u11, wb1[1]);
            wb0[2] = fmaf(a1.z, u10, wb0[2]); wb1[2] = fmaf(a1.z, u11, wb1[2]);
            wb0[3] = fmaf(a1.w, u10, wb0[3]); wb1[3] = fmaf(a1.w, u11, wb1[3]);
        }
        __syncwarp();   // logits reads of rwS done; safe to overwrite with w
        #pragma unroll
        for (int g = 0; g < 4; g++) {
            rwS[g * 68 + L]            = wa0[g];
            rwS[g * 68 + L + 32]       = wa1[g];
            rwS[272 + g * 68 + L]      = wb0[g];
            rwS[272 + g * 68 + L + 32] = wb1[g];
        }
        __syncwarp();

        // out[c] = w[g(c)] . Wv[:,c] + bv[c] ; lane owns ch 2L, 2L+1 (same group)
        {
            const int g = L >> 3;     // group of channel 2L (= (2L)>>4)
            const float* w0 = rwS + g * 68;
            const float* w1 = rwS + 272 + g * 68;
            float oa0 = bvS[2 * L], oa1 = bvS[2 * L + 1];
            float ob0 = oa0,        ob1 = oa1;
            #pragma unroll 8
            for (int e = 0; e < 64; e++) {
                float2 wv = *(const float2*)(WvS + e * 64 + 2 * L);
                float we0 = w0[e], we1 = w1[e];
                oa0 = fmaf(we0, wv.x, oa0); oa1 = fmaf(we0, wv.y, oa1);
                ob0 = fmaf(we1, wv.x, ob0); ob1 = fmaf(we1, wv.y, ob1);
            }
            *(float2*)(g_z + (size_t)tok0 * 64 + 2 * L)       = make_float2(oa0, oa1);
            *(float2*)(g_z + (size_t)(tok0 + 1) * 64 + 2 * L) = make_float2(ob0, ob1);
        }
        __syncwarp();   // protect per-warp tiles before next iteration
    }
}

// ===========================================================================
// Kernel B: LN1 -> MLP (exact gelu) -> LN2 -> + shortcut(x@Ws+bs)
// 8 tokens per warp (two 4-token halves a/b).  9 warps (288 thr, 227 regs).
// smem: weights 37504 | per warp (9): znTa 256|znTb 256|xTa 256|xTb 256|
//       hTa 512|hTb 512  (=2048)
// total = 37504 + 9*2048 = 55936 floats = 223744 B
// ===========================================================================
#define MTHREADS 288
#define MWARPS 9

__device__ __forceinline__ int hswz(int e) {   // conflict-free slot for hT
    return (e ^ ((e >> 3) & 3)) * 4;
}

__global__ __launch_bounds__(MTHREADS, 1)
void mlp_kernel(const float* __restrict__ x,
                const float* __restrict__ g1, const float* __restrict__ be1,
                const float* __restrict__ Wm1, const float* __restrict__ bm1,
                const float* __restrict__ Wm2, const float* __restrict__ bm2,
                const float* __restrict__ g2, const float* __restrict__ be2,
                const float* __restrict__ Ws, const float* __restrict__ bs,
                float* __restrict__ out)
{
    extern __shared__ float sm[];
    float* W1S  = sm;            // [e][256]
    float* W2S  = sm + 16384;    // [e][64]
    float* WsS  = sm + 32768;    // [e][64]
    float* bm1S = sm + 36864;
    float* bm2S = sm + 37120;
    float* bsS  = sm + 37184;
    float* g1S  = sm + 37248;
    float* be1S = sm + 37312;
    float* g2S  = sm + 37376;
    float* be2S = sm + 37440;

    const int tid = threadIdx.x;
    const int wid = tid >> 5;
    const int L   = tid & 31;

    float* wbase = sm + 37504 + wid * 2048;
    float* znTa = wbase;          // [ch][tok0-3]
    float* znTb = wbase + 256;    // [ch][tok4-7]
    float* xTa  = wbase + 512;
    float* xTb  = wbase + 768;
    float* hTa  = wbase + 1024;   // 128 ch x 4, swizzled (tok 0-3)
    float* hTb  = wbase + 1536;   // 128 ch x 4, swizzled (tok 4-7)

    for (int i = tid; i < 16384; i += MTHREADS) { W1S[i] = Wm1[i]; W2S[i] = Wm2[i]; }
    for (int i = tid; i < 4096;  i += MTHREADS) WsS[i] = Ws[i];
    if (tid < 256) bm1S[tid] = bm1[tid];
    if (tid < 64) {
        bm2S[tid] = bm2[tid]; bsS[tid] = bs[tid];
        g1S[tid] = g1[tid];   be1S[tid] = be1[tid];
        g2S[tid] = g2[tid];   be2S[tid] = be2[tid];
    }
    __syncthreads();

    const float g1a = g1S[2 * L],  g1b = g1S[2 * L + 1];
    const float b1a = be1S[2 * L], b1b = be1S[2 * L + 1];

    const int NGRP = NTOK / 8;
    for (int grp = blockIdx.x * MWARPS + wid; grp < NGRP; grp += GRID * MWARPS) {
        const int tok0 = grp * 8;
        const size_t base = (size_t)tok0 * 64;

        // ---- LN1 on 8 tokens (lane owns ch 2L, 2L+1) + stage x ----
        float zna[8], znb[8], xa[8], xb[8];
        #pragma unroll
        for (int t = 0; t < 8; t++) {
            float2 z = *(const float2*)(g_z + base + t * 64 + 2 * L);
            float mean = warpSum(z.x + z.y) * (1.f / 64.f);
            float d0 = z.x - mean, d1 = z.y - mean;
            float var = warpSum(d0 * d0 + d1 * d1) * (1.f / 64.f);
            float inv = rsqrtf(var + 1e-5f);
            zna[t] = d0 * inv * g1a + b1a;
            znb[t] = d1 * inv * g1b + b1b;
            float2 xv = *(const float2*)(x + base + t * 64 + 2 * L);
            xa[t] = xv.x; xb[t] = xv.y;
        }
        *(float4*)(znTa + 8 * L)     = make_float4(zna[0], zna[1], zna[2], zna[3]);
        *(float4*)(znTa + 8 * L + 4) = make_float4(znb[0], znb[1], znb[2], znb[3]);
        *(float4*)(znTb + 8 * L)     = make_float4(zna[4], zna[5], zna[6], zna[7]);
        *(float4*)(znTb + 8 * L + 4) = make_float4(znb[4], znb[5], znb[6], znb[7]);
        *(float4*)(xTa + 8 * L)      = make_float4(xa[0], xa[1], xa[2], xa[3]);
        *(float4*)(xTa + 8 * L + 4)  = make_float4(xb[0], xb[1], xb[2], xb[3]);
        *(float4*)(xTb + 8 * L)      = make_float4(xa[4], xa[5], xa[6], xa[7]);
        *(float4*)(xTb + 8 * L + 4)  = make_float4(xb[4], xb[5], xb[6], xb[7]);
        __syncwarp();

        // ---- h = zn @ Wm1 + bm1 ; lane owns d = 4L..4L+3 (j<4) and 128+4L..+3 (j>=4)
        float h[8][8];
        {
            float4 bA = *(const float4*)(bm1S + 4 * L);
            float4 bB = *(const float4*)(bm1S + 128 + 4 * L);
            #pragma unroll
            for (int t = 0; t < 8; t++) {
                h[t][0] = bA.x; h[t][1] = bA.y; h[t][2] = bA.z; h[t][3] = bA.w;
                h[t][4] = bB.x; h[t][5] = bB.y; h[t][6] = bB.z; h[t][7] = bB.w;
            }
        }
        #pragma unroll 4
        for (int e = 0; e < 64; e++) {
            float4 za4 = *(const float4*)(znTa + 4 * e);
            float4 zb4 = *(const float4*)(znTb + 4 * e);
            float4 wA = *(const float4*)(W1S + e * 256 + 4 * L);
            float4 wB = *(const float4*)(W1S + e * 256 + 128 + 4 * L);
            float za_[4] = {za4.x, za4.y, za4.z, za4.w};
            float zb_[4] = {zb4.x, zb4.y, zb4.z, zb4.w};
            float wA_[4] = {wA.x, wA.y, wA.z, wA.w};
            float wB_[4] = {wB.x, wB.y, wB.z, wB.w};
            #pragma unroll
            for (int t = 0; t < 4; t++) {
                #pragma unroll
                for (int j = 0; j < 4; j++) {
                    h[t][j]       = fmaf(za_[t], wA_[j], h[t][j]);
                    h[t][4 + j]   = fmaf(za_[t], wB_[j], h[t][4 + j]);
                    h[4 + t][j]     = fmaf(zb_[t], wA_[j], h[4 + t][j]);
                    h[4 + t][4 + j] = fmaf(zb_[t], wB_[j], h[4 + t][4 + j]);
                }
            }
        }

        // exact gelu
        #pragma unroll
        for (int t = 0; t < 8; t++) {
            #pragma unroll
            for (int j = 0; j < 8; j++)
                h[t][j] = 0.5f * h[t][j] * (1.f + erff(h[t][j] * 0.70710678118654752f));
        }

        // ---- o = h @ Wm2 + bm2 in two e-halves; lane owns ch 2L, 2L+1 ----
        float oA[8], oB[8];
        {
            float2 b2 = *(const float2*)(bm2S + 2 * L);
            #pragma unroll
            for (int t = 0; t < 8; t++) { oA[t] = b2.x; oB[t] = b2.y; }
        }
        // half 0: channels e in [0,128) = lane d 4L+j
        #pragma unroll
        for (int j = 0; j < 4; j++) {
            *(float4*)(hTa + hswz(4 * L + j)) = make_float4(h[0][j], h[1][j], h[2][j], h[3][j]);
            *(float4*)(hTb + hswz(4 * L + j)) = make_float4(h[4][j], h[5][j], h[6][j], h[7][j]);
        }
        __syncwarp();
        #pragma unroll 4
        for (int e = 0; e < 128; e++) {
            float4 ha = *(const float4*)(hTa + hswz(e));
            float4 hb = *(const float4*)(hTb + hswz(e));
            float2 w2 = *(const float2*)(W2S + e * 64 + 2 * L);
            oA[0]=fmaf(ha.x,w2.x,oA[0]); oB[0]=fmaf(ha.x,w2.y,oB[0]);
            oA[1]=fmaf(ha.y,w2.x,oA[1]); oB[1]=fmaf(ha.y,w2.y,oB[1]);
            oA[2]=fmaf(ha.z,w2.x,oA[2]); oB[2]=fmaf(ha.z,w2.y,oB[2]);
            oA[3]=fmaf(ha.w,w2.x,oA[3]); oB[3]=fmaf(ha.w,w2.y,oB[3]);
            oA[4]=fmaf(hb.x,w2.x,oA[4]); oB[4]=fmaf(hb.x,w2.y,oB[4]);
            oA[5]=fmaf(hb.y,w2.x,oA[5]); oB[5]=fmaf(hb.y,w2.y,oB[5]);
            oA[6]=fmaf(hb.z,w2.x,oA[6]); oB[6]=fmaf(hb.z,w2.y,oB[6]);
            oA[7]=fmaf(hb.w,w2.x,oA[7]); oB[7]=fmaf(hb.w,w2.y,oB[7]);
        }
        __syncwarp();
        // half 1: channels e in [128,256) = lane d 128+4L+j
        #pragma unroll
        for (int j = 0; j < 4; j++) {
            *(float4*)(hTa + hswz(4 * L + j)) = make_float4(h[0][4+j], h[1][4+j], h[2][4+j], h[3][4+j]);
            *(float4*)(hTb + hswz(4 * L + j)) = make_float4(h[4][4+j], h[5][4+j], h[6][4+j], h[7][4+j]);
        }
        __syncwarp();
        #pragma unroll 4
        for (int e = 0; e < 128; e++) {
            float4 ha = *(const float4*)(hTa + hswz(e));
            float4 hb = *(const float4*)(hTb + hswz(e));
            float2 w2 = *(const float2*)(W2S + (e + 128) * 64 + 2 * L);
            oA[0]=fmaf(ha.x,w2.x,oA[0]); oB[0]=fmaf(ha.x,w2.y,oB[0]);
            oA[1]=fmaf(ha.y,w2.x,oA[1]); oB[1]=fmaf(ha.y,w2.y,oB[1]);
            oA[2]=fmaf(ha.z,w2.x,oA[2]); oB[2]=fmaf(ha.z,w2.y,oB[2]);
            oA[3]=fmaf(ha.w,w2.x,oA[3]); oB[3]=fmaf(ha.w,w2.y,oB[3]);
            oA[4]=fmaf(hb.x,w2.x,oA[4]); oB[4]=fmaf(hb.x,w2.y,oB[4]);
            oA[5]=fmaf(hb.y,w2.x,oA[5]); oB[5]=fmaf(hb.y,w2.y,oB[5]);
            oA[6]=fmaf(hb.z,w2.x,oA[6]); oB[6]=fmaf(hb.z,w2.y,oB[6]);
            oA[7]=fmaf(hb.w,w2.x,oA[7]); oB[7]=fmaf(hb.w,w2.y,oB[7]);
        }

        // ---- shortcut = x @ Ws + bs ----
        float sA[8], sB[8];
        {
            float2 b2 = *(const float2*)(bsS + 2 * L);
            #pragma unroll
            for (int t = 0; t < 8; t++) { sA[t] = b2.x; sB[t] = b2.y; }
        }
        #pragma unroll 4
        for (int e = 0; e < 64; e++) {
            float4 x4a = *(const float4*)(xTa + 4 * e);
            float4 x4b = *(const float4*)(xTb + 4 * e);
            float2 ws = *(const float2*)(WsS + e * 64 + 2 * L);
            sA[0]=fmaf(x4a.x,ws.x,sA[0]); sB[0]=fmaf(x4a.x,ws.y,sB[0]);
            sA[1]=fmaf(x4a.y,ws.x,sA[1]); sB[1]=fmaf(x4a.y,ws.y,sB[1]);
            sA[2]=fmaf(x4a.z,ws.x,sA[2]); sB[2]=fmaf(x4a.z,ws.y,sB[2]);
            sA[3]=fmaf(x4a.w,ws.x,sA[3]); sB[3]=fmaf(x4a.w,ws.y,sB[3]);
            sA[4]=fmaf(x4b.x,ws.x,sA[4]); sB[4]=fmaf(x4b.x,ws.y,sB[4]);
            sA[5]=fmaf(x4b.y,ws.x,sA[5]); sB[5]=fmaf(x4b.y,ws.y,sB[5]);
            sA[6]=fmaf(x4b.z,ws.x,sA[6]); sB[6]=fmaf(x4b.z,ws.y,sB[6]);
            sA[7]=fmaf(x4b.w,ws.x,sA[7]); sB[7]=fmaf(x4b.w,ws.y,sB[7]);
        }

        // ---- LN2 + add shortcut, store ----
        #pragma unroll
        for (int t = 0; t < 8; t++) {
            float m2 = warpSum(oA[t] + oB[t]) * (1.f / 64.f);
            float e0 = oA[t] - m2, e1 = oB[t] - m2;
            float v2 = warpSum(e0 * e0 + e1 * e1) * (1.f / 64.f);
            float inv2 = rsqrtf(v2 + 1e-5f);
            float on0 = e0 * inv2 * g2S[2 * L]     + be2S[2 * L];
            float on1 = e1 * inv2 * g2S[2 * L + 1] + be2S[2 * L + 1];
            *(float2*)(out + base + t * 64 + 2 * L) = make_float2(on0 + sA[t], on1 + sB[t]);
        }
        __syncwarp();   // protect tiles before next group
    }
}

// ===========================================================================
extern "C" void kernel_launch(void* const* d_in, const int* in_sizes, int n_in,
                              void* d_out, int out_size)
{
    const float* u   = (const float*)d_in[0];
    const float* x   = (const float*)d_in[1];
    const float* Wk  = (const float*)d_in[2];
    const float* bk  = (const float*)d_in[3];
    const float* Wq  = (const float*)d_in[4];
    const float* bq  = (const float*)d_in[5];
    const float* Wv  = (const float*)d_in[6];
    const float* bv  = (const float*)d_in[7];
    const float* g1  = (const float*)d_in[8];
    const float* be1 = (const float*)d_in[9];
    const float* Wm1 = (const float*)d_in[10];
    const float* bm1 = (const float*)d_in[11];
    const float* Wm2 = (const float*)d_in[12];
    const float* bm2 = (const float*)d_in[13];
    const float* g2  = (const float*)d_in[14];
    const float* be2 = (const float*)d_in[15];
    const float* Ws  = (const float*)d_in[16];
    const float* bs  = (const float*)d_in[17];
    float* out = (float*)d_out;

    const int smemA = 55936 * 4;   // 223744 B
    const int smemB = 55936 * 4;   // 223744 B
    cudaFuncSetAttribute(attn_kernel, cudaFuncAttributeMaxDynamicSharedMemorySize, smemA);
    cudaFuncSetAttribute(mlp_kernel,  cudaFuncAttributeMaxDynamicSharedMemorySize, smemB);

    attn_kernel<<<GRID, ATHREADS, smemA>>>(u, x, Wk, bk, Wq, bq, Wv, bv);
    mlp_kernel<<<GRID, MTHREADS, smemB>>>(x, g1, be1, Wm1, bm1, Wm2, bm2,
                                          g2, be2, Ws, bs, out);
}

// round 14
// speedup vs baseline: 1.9839x; 1.0755x over previous
#include <cuda_runtime.h>
#include <math.h>

// Problem constants
#define BB 8
#define NN 7168
#define NTOK (BB*NN)            // 57344
#define UU 49152
#define GRID 148

__device__ float g_z[(size_t)NTOK * 64];   // attention output scratch (pre-LN)

__device__ __forceinline__ float warpSum(float v) {
    v += __shfl_xor_sync(0xffffffffu, v, 16);
    v += __shfl_xor_sync(0xffffffffu, v, 8);
    v += __shfl_xor_sync(0xffffffffu, v, 4);
    v += __shfl_xor_sync(0xffffffffu, v, 2);
    v += __shfl_xor_sync(0xffffffffu, v, 1);
    return v;
}

// ===========================================================================
// Kernel A: bunched grouped cross-attention -> g_z.  Token-PAIR per warp.
// In-register butterfly softmax.  (UNCHANGED from R12: 110us measured)
// total smem = 12480 + 14*3104 = 55936 floats = 223744 B
// ===========================================================================
#define ATHREADS 448
#define AWARPS 14

__global__ __launch_bounds__(ATHREADS, 1)
void attn_kernel(const float* __restrict__ u, const float* __restrict__ x,
                 const float* __restrict__ Wk, const float* __restrict__ bk,
                 const float* __restrict__ Wq, const float* __restrict__ bq,
                 const float* __restrict__ Wv, const float* __restrict__ bv)
{
    extern __shared__ float sm[];
    float* WqS  = sm;
    float* WkTS = sm + 4096;
    float* WvS  = sm + 8192;
    float* bqS  = sm + 12288;
    float* bkS  = sm + 12352;
    float* bvS  = sm + 12416;

    const int tid = threadIdx.x;
    const int wid = tid >> 5;
    const int L   = tid & 31;

    float* warpS = sm + 12480 + wid * 3104;
    float* uS  = warpS;          // 32 x 68
    float* rwS = warpS + 2176;   // 2 tokens x 4 x 68 (r, later w)
    float* qS  = warpS + 2720;   // [ch][tok] 64 x 2
    float* xT  = warpS + 2848;   // [ch][tok] 64 x 2
    float* atS = warpS + 2976;   // 128 attn

    for (int i = tid; i < 4096; i += ATHREADS) {
        WqS[i] = Wq[i];
        WvS[i] = Wv[i];
        WkTS[(i & 63) * 64 + (i >> 6)] = Wk[i];   // transpose Wk -> [d][e]
    }
    if (tid < 64) { bqS[tid] = bq[tid]; bkS[tid] = bk[tid]; bvS[tid] = bv[tid]; }
    __syncthreads();

    const int NPAIR = NTOK / 2;
    for (int pair = blockIdx.x * AWARPS + wid; pair < NPAIR; pair += GRID * AWARPS) {
        const int tok0 = pair * 2;
        const int b = tok0 / NN;
        const int n = tok0 - b * NN;          // even

        int to, urow;
        if (n < 4096) {                       // bunch 0: rel=2, to=4
            to = 4;
            urow = (n < 2048) ? (n * 4) : (24576 + (n - 2048) * 4);
        } else if (n < 6144) {                // bunch 1: rel=4, to=8
            int m = n - 4096;
            to = 8;
            urow = (m < 1024) ? (8192 + m * 8) : (32768 + (m - 1024) * 8);
        } else {                              // bunch 2: rel=8, to=16
            int m = n - 6144;
            to = 16;
            urow = (m < 512) ? (16384 + m * 16) : (40960 + (m - 512) * 16);
        }
        // token n+1 uses rows [urow+to, urow+2*to) -> contiguous 2*to rows

        const float* xr = x + (size_t)tok0 * 64;
        const float4* ur4 = (const float4*)(u + ((size_t)b * UU + (size_t)urow) * 64);

        // stage u tile: 2*to rows of 64 floats, padded stride 68
        const int cnt4 = 2 * to * 16;
        #pragma unroll 4
        for (int i4 = L; i4 < cnt4; i4 += 32) {
            float4 v = ur4[i4];
            *((float4*)(uS + (i4 >> 4) * 68) + (i4 & 15)) = v;
        }

        // stage x transposed: xT[ch][tok]
        {
            float2 xa = *(const float2*)(xr + 2 * L);
            float2 xb = *(const float2*)(xr + 64 + 2 * L);
            float4 st = make_float4(xa.x, xb.x, xa.y, xb.y);
            *(float4*)(xT + 4 * L) = st;
        }
        __syncwarp();

        // q = x @ Wq + bq for both tokens; lane owns ch 2L, 2L+1
        float qa0 = bqS[2 * L], qa1 = bqS[2 * L + 1];
        float qb0 = qa0,        qb1 = qa1;
        #pragma unroll 8
        for (int e = 0; e < 64; e++) {
            float2 xe = *(const float2*)(xT + 2 * e);        // (x0[e], x1[e]) bcast
            float2 w  = *(const float2*)(WqS + e * 64 + 2 * L);
            qa0 = fmaf(xe.x, w.x, qa0); qa1 = fmaf(xe.x, w.y, qa1);
            qb0 = fmaf(xe.y, w.x, qb0); qb1 = fmaf(xe.y, w.y, qb1);
        }
        *(float4*)(qS + 4 * L) = make_float4(qa0, qb0, qa1, qb1);  // qS[ch][tok]
        __syncwarp();

        // r[t][g][e] (e = L, L+32) and s[t][g]
        float s0_0, s0_1, s0_2, s0_3, s1_0, s1_1, s1_2, s1_3;
        #pragma unroll
        for (int g = 0; g < 4; g++) {
            float ra0 = 0.f, ra1 = 0.f, rb0 = 0.f, rb1 = 0.f, sa = 0.f, sb = 0.f;
            #pragma unroll
            for (int dd = 0; dd < 16; dd++) {
                const int d = g * 16 + dd;
                float2 qd = *(const float2*)(qS + 2 * d);    // (q0[d], q1[d]) bcast
                float wkl = WkTS[d * 64 + L];
                float wkh = WkTS[d * 64 + L + 32];
                float bkd = bkS[d];
                ra0 = fmaf(wkl, qd.x, ra0); ra1 = fmaf(wkh, qd.x, ra1);
                rb0 = fmaf(wkl, qd.y, rb0); rb1 = fmaf(wkh, qd.y, rb1);
                sa  = fmaf(bkd, qd.x, sa);  sb  = fmaf(bkd, qd.y, sb);
            }
            rwS[g * 68 + L]            = ra0;
            rwS[g * 68 + L + 32]       = ra1;
            rwS[272 + g * 68 + L]      = rb0;
            rwS[272 + g * 68 + L + 32] = rb1;
            if (g == 0) { s0_0 = sa; s1_0 = sb; }
            else if (g == 1) { s0_1 = sa; s1_1 = sb; }
            else if (g == 2) { s0_2 = sa; s1_2 = sb; }
            else { s0_3 = sa; s1_3 = sb; }
        }
        __syncwarp();

        // logits in registers: lg[rep], rep < nrep = to/4; p = rep*32+L = t2*4+g
        const int nrep = to >> 2;
        float lg[4];
        #pragma unroll
        for (int rep = 0; rep < 4; rep++) {
            if (rep < nrep) {
                int p = rep * 32 + L;
                int t2 = p >> 2, g = p & 3;
                int tk = (t2 >= to);
                float acc = tk ? ((g == 0) ? s1_0 : (g == 1) ? s1_1 : (g == 2) ? s1_2 : s1_3)
                               : ((g == 0) ? s0_0 : (g == 1) ? s0_1 : (g == 2) ? s0_2 : s0_3);
                const float4* up = (const float4*)(uS + t2 * 68);
                const float4* rp = (const float4*)(rwS + tk * 272 + g * 68);
                #pragma unroll
                for (int e4 = 0; e4 < 16; e4++) {
                    float4 a = up[e4], bb = rp[e4];
                    acc = fmaf(a.x, bb.x, acc);
                    acc = fmaf(a.y, bb.y, acc);
                    acc = fmaf(a.z, bb.z, acc);
                    acc = fmaf(a.w, bb.w, acc);
                }
                lg[rep] = acc * 0.125f;
            }
        }

        // in-register softmax over t per (token, group), butterfly shfl
        if (to == 4) {
            float m = lg[0];
            m = fmaxf(m, __shfl_xor_sync(0xffffffffu, m, 4));
            m = fmaxf(m, __shfl_xor_sync(0xffffffffu, m, 8));
            float e = expf(lg[0] - m);
            float s = e;
            s += __shfl_xor_sync(0xffffffffu, s, 4);
            s += __shfl_xor_sync(0xffffffffu, s, 8);
            atS[L] = e / s;
        } else if (to == 8) {
            #pragma unroll
            for (int rep = 0; rep < 2; rep++) {
                float m = lg[rep];
                m = fmaxf(m, __shfl_xor_sync(0xffffffffu, m, 4));
                m = fmaxf(m, __shfl_xor_sync(0xffffffffu, m, 8));
                m = fmaxf(m, __shfl_xor_sync(0xffffffffu, m, 16));
                float e = expf(lg[rep] - m);
                float s = e;
                s += __shfl_xor_sync(0xffffffffu, s, 4);
                s += __shfl_xor_sync(0xffffffffu, s, 8);
                s += __shfl_xor_sync(0xffffffffu, s, 16);
                atS[rep * 32 + L] = e / s;
            }
        } else {
            #pragma unroll
            for (int half = 0; half < 2; half++) {
                float la = lg[half * 2], lb = lg[half * 2 + 1];
                float m = fmaxf(la, lb);
                m = fmaxf(m, __shfl_xor_sync(0xffffffffu, m, 4));
                m = fmaxf(m, __shfl_xor_sync(0xffffffffu, m, 8));
                m = fmaxf(m, __shfl_xor_sync(0xffffffffu, m, 16));
                float ea = expf(la - m), eb = expf(lb - m);
                float s = ea + eb;
                s += __shfl_xor_sync(0xffffffffu, s, 4);
                s += __shfl_xor_sync(0xffffffffu, s, 8);
                s += __shfl_xor_sync(0xffffffffu, s, 16);
                float is = 1.f / s;
                atS[half * 64 + L]      = ea * is;
                atS[half * 64 + 32 + L] = eb * is;
            }
        }
        __syncwarp();

        // w[t][g][e] = sum_t attn * u ; e = L, L+32
        float wa0[4] = {0.f,0.f,0.f,0.f}, wa1[4] = {0.f,0.f,0.f,0.f};
        float wb0[4] = {0.f,0.f,0.f,0.f}, wb1[4] = {0.f,0.f,0.f,0.f};
        #pragma unroll 4
        for (int t = 0; t < to; t++) {
            float4 a0 = *(const float4*)(atS + t * 4);
            float4 a1 = *(const float4*)(atS + (to + t) * 4);
            float u00 = uS[t * 68 + L],        u01 = uS[t * 68 + L + 32];
            float u10 = uS[(to + t) * 68 + L], u11 = uS[(to + t) * 68 + L + 32];
            wa0[0] = fmaf(a0.x, u00, wa0[0]); wa1[0] = fmaf(a0.x, u01, wa1[0]);
            wa0[1] = fmaf(a0.y, u00, wa0[1]); wa1[1] = fmaf(a0.y, u01, wa1[1]);
            wa0[2] = fmaf(a0.z, u00, wa0[2]); wa1[2] = fmaf(a0.z, u01, wa1[2]);
            wa0[3] = fmaf(a0.w, u00, wa0[3]); wa1[3] = fmaf(a0.w, u01, wa1[3]);
            wb0[0] = fmaf(a1.x, u10, wb0[0]); wb1[0] = fmaf(a1.x, u11, wb1[0]);
            wb0[1] = fmaf(a1.y, u10, wb0[1]); wb1[1] = fmaf(a1.y, u11, wb1[1]);
            wb0[2] = fmaf(a1.z, u10, wb0[2]); wb1[2] = fmaf(a1.z, u11, wb1[2]);
            wb0[3] = fmaf(a1.w, u10, wb0[3]); wb1[3] = fmaf(a1.w, u11, wb1[3]);
        }
        __syncwarp();   // logits reads of rwS done; safe to overwrite with w
        #pragma unroll
        for (int g = 0; g < 4; g++) {
            rwS[g * 68 + L]            = wa0[g];
            rwS[g * 68 + L + 32]       = wa1[g];
            rwS[272 + g * 68 + L]      = wb0[g];
            rwS[272 + g * 68 + L + 32] = wb1[g];
        }
        __syncwarp();

        // out[c] = w[g(c)] . Wv[:,c] + bv[c] ; lane owns ch 2L, 2L+1 (same group)
        {
            const int g = L >> 3;     // group of channel 2L (= (2L)>>4)
            const float* w0 = rwS + g * 68;
            const float* w1 = rwS + 272 + g * 68;
            float oa0 = bvS[2 * L], oa1 = bvS[2 * L + 1];
            float ob0 = oa0,        ob1 = oa1;
            #pragma unroll 8
            for (int e = 0; e < 64; e++) {
                float2 wv = *(const float2*)(WvS + e * 64 + 2 * L);
                float we0 = w0[e], we1 = w1[e];
                oa0 = fmaf(we0, wv.x, oa0); oa1 = fmaf(we0, wv.y, oa1);
                ob0 = fmaf(we1, wv.x, ob0); ob1 = fmaf(we1, wv.y, ob1);
            }
            *(float2*)(g_z + (size_t)tok0 * 64 + 2 * L)       = make_float2(oa0, oa1);
            *(float2*)(g_z + (size_t)(tok0 + 1) * 64 + 2 * L) = make_float2(ob0, ob1);
        }
        __syncwarp();   // protect per-warp tiles before next iteration
    }
}

// ===========================================================================
// Kernel B: LN1 -> MLP (exact gelu) -> LN2 -> + shortcut(x@Ws+bs)
// 4 tokens/warp (R6-proven, 114 regs), now 14 warps (448 thr; cap 146 regs).
// One-pass LN (var = E[z^2] - mean^2): interleaved independent shfl chains.
// smem: weights 37504 | per warp (14): znT 256 | xT 256 | hT 512 (=1024)
// total = 37504 + 14*1024 = 51840 floats = 207360 B
// ===========================================================================
#define MTHREADS 448
#define MWARPS 14

__device__ __forceinline__ int hswz(int e) {   // conflict-free slot for hT
    return (e ^ ((e >> 3) & 3)) * 4;
}

__global__ __launch_bounds__(MTHREADS, 1)
void mlp_kernel(const float* __restrict__ x,
                const float* __restrict__ g1, const float* __restrict__ be1,
                const float* __restrict__ Wm1, const float* __restrict__ bm1,
                const float* __restrict__ Wm2, const float* __restrict__ bm2,
                const float* __restrict__ g2, const float* __restrict__ be2,
                const float* __restrict__ Ws, const float* __restrict__ bs,
                float* __restrict__ out)
{
    extern __shared__ float sm[];
    float* W1S  = sm;            // [e][256]
    float* W2S  = sm + 16384;    // [e][64]
    float* WsS  = sm + 32768;    // [e][64]
    float* bm1S = sm + 36864;
    float* bm2S = sm + 37120;
    float* bsS  = sm + 37184;
    float* g1S  = sm + 37248;
    float* be1S = sm + 37312;
    float* g2S  = sm + 37376;
    float* be2S = sm + 37440;

    const int tid = threadIdx.x;
    const int wid = tid >> 5;
    const int L   = tid & 31;

    float* wbase = sm + 37504 + wid * 1024;
    float* znT = wbase;          // [ch][4]
    float* xT  = wbase + 256;    // [ch][4]
    float* hT  = wbase + 512;    // 128 x 4, swizzled

    for (int i = tid; i < 16384; i += MTHREADS) { W1S[i] = Wm1[i]; W2S[i] = Wm2[i]; }
    for (int i = tid; i < 4096;  i += MTHREADS) WsS[i] = Ws[i];
    if (tid < 256) bm1S[tid] = bm1[tid];
    if (tid < 64) {
        bm2S[tid] = bm2[tid]; bsS[tid] = bs[tid];
        g1S[tid] = g1[tid];   be1S[tid] = be1[tid];
        g2S[tid] = g2[tid];   be2S[tid] = be2[tid];
    }
    __syncthreads();

    const int NGRP = NTOK / 4;
    for (int grp = blockIdx.x * MWARPS + wid; grp < NGRP; grp += GRID * MWARPS) {
        const int tok0 = grp * 4;
        const size_t base = (size_t)tok0 * 64;

        // ---- LN1 on 4 tokens (lane owns ch L, L+32); one-pass form ----
        float zn0[4], zn1[4];
        #pragma unroll
        for (int t = 0; t < 4; t++) {
            float z0 = g_z[base + t * 64 + L];
            float z1 = g_z[base + t * 64 + L + 32];
            float s1 = warpSum(z0 + z1);
            float s2 = warpSum(fmaf(z0, z0, z1 * z1));
            float mean = s1 * (1.f / 64.f);
            float var  = fmaf(-mean, mean, s2 * (1.f / 64.f));
            float inv = rsqrtf(var + 1e-5f);
            zn0[t] = (z0 - mean) * inv * g1S[L]      + be1S[L];
            zn1[t] = (z1 - mean) * inv * g1S[L + 32] + be1S[L + 32];
        }
        *(float4*)(znT + 4 * L)        = make_float4(zn0[0], zn0[1], zn0[2], zn0[3]);
        *(float4*)(znT + 4 * (L + 32)) = make_float4(zn1[0], zn1[1], zn1[2], zn1[3]);

        // stage x transposed for the shortcut
        {
            float xa[4], xb[4];
            #pragma unroll
            for (int t = 0; t < 4; t++) {
                xa[t] = x[base + t * 64 + L];
                xb[t] = x[base + t * 64 + L + 32];
            }
            *(float4*)(xT + 4 * L)        = make_float4(xa[0], xa[1], xa[2], xa[3]);
            *(float4*)(xT + 4 * (L + 32)) = make_float4(xb[0], xb[1], xb[2], xb[3]);
        }
        __syncwarp();

        // ---- h = zn @ Wm1 + bm1 ; lane owns d = 4L..4L+3 and 128+4L..+3 ----
        float h0[8], h1[8], h2[8], h3[8];
        {
            float4 bA = *(const float4*)(bm1S + 4 * L);
            float4 bB = *(const float4*)(bm1S + 128 + 4 * L);
            h0[0]=bA.x; h0[1]=bA.y; h0[2]=bA.z; h0[3]=bA.w;
            h0[4]=bB.x; h0[5]=bB.y; h0[6]=bB.z; h0[7]=bB.w;
            #pragma unroll
            for (int j = 0; j < 8; j++) { h1[j]=h0[j]; h2[j]=h0[j]; h3[j]=h0[j]; }
        }
        #pragma unroll 4
        for (int e = 0; e < 64; e++) {
            float4 zn4 = *(const float4*)(znT + 4 * e);      // 4 tokens, bcast
            float4 wA = *(const float4*)(W1S + e * 256 + 4 * L);
            float4 wB = *(const float4*)(W1S + e * 256 + 128 + 4 * L);
            h0[0]=fmaf(zn4.x,wA.x,h0[0]); h0[1]=fmaf(zn4.x,wA.y,h0[1]);
            h0[2]=fmaf(zn4.x,wA.z,h0[2]); h0[3]=fmaf(zn4.x,wA.w,h0[3]);
            h0[4]=fmaf(zn4.x,wB.x,h0[4]); h0[5]=fmaf(zn4.x,wB.y,h0[5]);
            h0[6]=fmaf(zn4.x,wB.z,h0[6]); h0[7]=fmaf(zn4.x,wB.w,h0[7]);
            h1[0]=fmaf(zn4.y,wA.x,h1[0]); h1[1]=fmaf(zn4.y,wA.y,h1[1]);
            h1[2]=fmaf(zn4.y,wA.z,h1[2]); h1[3]=fmaf(zn4.y,wA.w,h1[3]);
            h1[4]=fmaf(zn4.y,wB.x,h1[4]); h1[5]=fmaf(zn4.y,wB.y,h1[5]);
            h1[6]=fmaf(zn4.y,wB.z,h1[6]); h1[7]=fmaf(zn4.y,wB.w,h1[7]);
            h2[0]=fmaf(zn4.z,wA.x,h2[0]); h2[1]=fmaf(zn4.z,wA.y,h2[1]);
            h2[2]=fmaf(zn4.z,wA.z,h2[2]); h2[3]=fmaf(zn4.z,wA.w,h2[3]);
            h2[4]=fmaf(zn4.z,wB.x,h2[4]); h2[5]=fmaf(zn4.z,wB.y,h2[5]);
            h2[6]=fmaf(zn4.z,wB.z,h2[6]); h2[7]=fmaf(zn4.z,wB.w,h2[7]);
            h3[0]=fmaf(zn4.w,wA.x,h3[0]); h3[1]=fmaf(zn4.w,wA.y,h3[1]);
            h3[2]=fmaf(zn4.w,wA.z,h3[2]); h3[3]=fmaf(zn4.w,wA.w,h3[3]);
            h3[4]=fmaf(zn4.w,wB.x,h3[4]); h3[5]=fmaf(zn4.w,wB.y,h3[5]);
            h3[6]=fmaf(zn4.w,wB.z,h3[6]); h3[7]=fmaf(zn4.w,wB.w,h3[7]);
        }

        // exact gelu
        #pragma unroll
        for (int j = 0; j < 8; j++) {
            h0[j] = 0.5f * h0[j] * (1.f + erff(h0[j] * 0.70710678118654752f));
            h1[j] = 0.5f * h1[j] * (1.f + erff(h1[j] * 0.70710678118654752f));
            h2[j] = 0.5f * h2[j] * (1.f + erff(h2[j] * 0.70710678118654752f));
            h3[j] = 0.5f * h3[j] * (1.f + erff(h3[j] * 0.70710678118654752f));
        }

        // ---- o = h @ Wm2 + bm2 in two e-halves; lane owns ch 2L, 2L+1 ----
        float o0[4], o1[4];
        {
            float2 b2 = *(const float2*)(bm2S + 2 * L);
            #pragma unroll
            for (int t = 0; t < 4; t++) { o0[t] = b2.x; o1[t] = b2.y; }
        }
        // half 0: channels e in [0,128)
        #pragma unroll
        for (int j = 0; j < 4; j++)
            *(float4*)(hT + hswz(4 * L + j)) = make_float4(h0[j], h1[j], h2[j], h3[j]);
        __syncwarp();
        #pragma unroll 4
        for (int e = 0; e < 128; e++) {
            float4 hv = *(const float4*)(hT + hswz(e));
            float2 w2 = *(const float2*)(W2S + e * 64 + 2 * L);
            o0[0]=fmaf(hv.x,w2.x,o0[0]); o1[0]=fmaf(hv.x,w2.y,o1[0]);
            o0[1]=fmaf(hv.y,w2.x,o0[1]); o1[1]=fmaf(hv.y,w2.y,o1[1]);
            o0[2]=fmaf(hv.z,w2.x,o0[2]); o1[2]=fmaf(hv.z,w2.y,o1[2]);
            o0[3]=fmaf(hv.w,w2.x,o0[3]); o1[3]=fmaf(hv.w,w2.y,o1[3]);
        }
        __syncwarp();
        // half 1: channels e in [128,256)
        #pragma unroll
        for (int j = 0; j < 4; j++)
            *(float4*)(hT + hswz(4 * L + j)) = make_float4(h0[4+j], h1[4+j], h2[4+j], h3[4+j]);
        __syncwarp();
        #pragma unroll 4
        for (int e = 0; e < 128; e++) {
            float4 hv = *(const float4*)(hT + hswz(e));
            float2 w2 = *(const float2*)(W2S + (e + 128) * 64 + 2 * L);
            o0[0]=fmaf(hv.x,w2.x,o0[0]); o1[0]=fmaf(hv.x,w2.y,o1[0]);
            o0[1]=fmaf(hv.y,w2.x,o0[1]); o1[1]=fmaf(hv.y,w2.y,o1[1]);
            o0[2]=fmaf(hv.z,w2.x,o0[2]); o1[2]=fmaf(hv.z,w2.y,o1[2]);
            o0[3]=fmaf(hv.w,w2.x,o0[3]); o1[3]=fmaf(hv.w,w2.y,o1[3]);
        }

        // ---- shortcut = x @ Ws + bs ----
        float sc0[4], sc1[4];
        {
            float2 b2 = *(const float2*)(bsS + 2 * L);
            #pragma unroll
            for (int t = 0; t < 4; t++) { sc0[t] = b2.x; sc1[t] = b2.y; }
        }
        #pragma unroll 4
        for (int e = 0; e < 64; e++) {
            float4 xe = *(const float4*)(xT + 4 * e);
            float2 ws = *(const float2*)(WsS + e * 64 + 2 * L);
            sc0[0]=fmaf(xe.x,ws.x,sc0[0]); sc1[0]=fmaf(xe.x,ws.y,sc1[0]);
            sc0[1]=fmaf(xe.y,ws.x,sc0[1]); sc1[1]=fmaf(xe.y,ws.y,sc1[1]);
            sc0[2]=fmaf(xe.z,ws.x,sc0[2]); sc1[2]=fmaf(xe.z,ws.y,sc1[2]);
            sc0[3]=fmaf(xe.w,ws.x,sc0[3]); sc1[3]=fmaf(xe.w,ws.y,sc1[3]);
        }

        // ---- LN2 (one-pass) + add shortcut, store ----
        #pragma unroll
        for (int t = 0; t < 4; t++) {
            float s1 = warpSum(o0[t] + o1[t]);
            float s2 = warpSum(fmaf(o0[t], o0[t], o1[t] * o1[t]));
            float m2 = s1 * (1.f / 64.f);
            float v2 = fmaf(-m2, m2, s2 * (1.f / 64.f));
            float inv2 = rsqrtf(v2 + 1e-5f);
            float on0 = (o0[t] - m2) * inv2 * g2S[2 * L]     + be2S[2 * L];
            float on1 = (o1[t] - m2) * inv2 * g2S[2 * L + 1] + be2S[2 * L + 1];
            *(float2*)(out + base + t * 64 + 2 * L) = make_float2(on0 + sc0[t], on1 + sc1[t]);
        }
        __syncwarp();   // protect tiles before next group
    }
}

// ===========================================================================
extern "C" void kernel_launch(void* const* d_in, const int* in_sizes, int n_in,
                              void* d_out, int out_size)
{
    const float* u   = (const float*)d_in[0];
    const float* x   = (const float*)d_in[1];
    const float* Wk  = (const float*)d_in[2];
    const float* bk  = (const float*)d_in[3];
    const float* Wq  = (const float*)d_in[4];
    const float* bq  = (const float*)d_in[5];
    const float* Wv  = (const float*)d_in[6];
    const float* bv  = (const float*)d_in[7];
    const float* g1  = (const float*)d_in[8];
    const float* be1 = (const float*)d_in[9];
    const float* Wm1 = (const float*)d_in[10];
    const float* bm1 = (const float*)d_in[11];
    const float* Wm2 = (const float*)d_in[12];
    const float* bm2 = (const float*)d_in[13];
    const float* g2  = (const float*)d_in[14];
    const float* be2 = (const float*)d_in[15];
    const float* Ws  = (const float*)d_in[16];
    const float* bs  = (const float*)d_in[17];
    float* out = (float*)d_out;

    const int smemA = 55936 * 4;   // 223744 B
    const int smemB = 51840 * 4;   // 207360 B
    cudaFuncSetAttribute(attn_kernel, cudaFuncAttributeMaxDynamicSharedMemorySize, smemA);
    cudaFuncSetAttribute(mlp_kernel,  cudaFuncAttributeMaxDynamicSharedMemorySize, smemB);

    attn_kernel<<<GRID, ATHREADS, smemA>>>(u, x, Wk, bk, Wq, bq, Wv, bv);
    mlp_kernel<<<GRID, MTHREADS, smemB>>>(x, g1, be1, Wm1, bm1, Wm2, bm2,
                                          g2, be2, Ws, bs, out);
}

// round 15
// speedup vs baseline: 2.0662x; 1.0415x over previous
#include <cuda_runtime.h>
#include <math.h>

// Problem constants
#define BB 8
#define NN 7168
#define NTOK (BB*NN)            // 57344
#define UU 49152
#define GRID 148

__device__ float g_z[(size_t)NTOK * 64];   // attention output scratch (pre-LN)

__device__ __forceinline__ float warpSum(float v) {
    v += __shfl_xor_sync(0xffffffffu, v, 16);
    v += __shfl_xor_sync(0xffffffffu, v, 8);
    v += __shfl_xor_sync(0xffffffffu, v, 4);
    v += __shfl_xor_sync(0xffffffffu, v, 2);
    v += __shfl_xor_sync(0xffffffffu, v, 1);
    return v;
}

// ---- packed f32x2 helpers (FFMA2: 2 fp32 FMAs per instruction) ----
__device__ __forceinline__ unsigned long long dup2(float v) {
    unsigned long long r;
    unsigned int b = __float_as_uint(v);
    asm("mov.b64 %0, {%1, %2};" : "=l"(r) : "r"(b), "r"(b));
    return r;
}
__device__ __forceinline__ unsigned long long ffma2(unsigned long long a,
                                                    unsigned long long b,
                                                    unsigned long long c) {
    unsigned long long d;
    asm("fma.rn.f32x2 %0, %1, %2, %3;" : "=l"(d) : "l"(a), "l"(b), "l"(c));
    return d;
}
__device__ __forceinline__ float2 unpk2(unsigned long long v) {
    unsigned int lo, hi;
    asm("mov.b64 {%0, %1}, %2;" : "=r"(lo), "=r"(hi) : "l"(v));
    return make_float2(__uint_as_float(lo), __uint_as_float(hi));
}

// ===========================================================================
// Kernel A: bunched grouped cross-attention -> g_z.  Token-PAIR per warp.
// Butterfly softmax; logits dot now uses FFMA2 (both operands pre-packed).
// total smem = 12480 + 14*3104 = 55936 floats = 223744 B
// ===========================================================================
#define ATHREADS 448
#define AWARPS 14

__global__ __launch_bounds__(ATHREADS, 1)
void attn_kernel(const float* __restrict__ u, const float* __restrict__ x,
                 const float* __restrict__ Wk, const float* __restrict__ bk,
                 const float* __restrict__ Wq, const float* __restrict__ bq,
                 const float* __restrict__ Wv, const float* __restrict__ bv)
{
    extern __shared__ float sm[];
    float* WqS  = sm;
    float* WkTS = sm + 4096;
    float* WvS  = sm + 8192;
    float* bqS  = sm + 12288;
    float* bkS  = sm + 12352;
    float* bvS  = sm + 12416;

    const int tid = threadIdx.x;
    const int wid = tid >> 5;
    const int L   = tid & 31;

    float* warpS = sm + 12480 + wid * 3104;
    float* uS  = warpS;          // 32 x 68
    float* rwS = warpS + 2176;   // 2 tokens x 4 x 68 (r, later w)
    float* qS  = warpS + 2720;   // [ch][tok] 64 x 2
    float* xT  = warpS + 2848;   // [ch][tok] 64 x 2
    float* atS = warpS + 2976;   // 128 attn

    for (int i = tid; i < 4096; i += ATHREADS) {
        WqS[i] = Wq[i];
        WvS[i] = Wv[i];
        WkTS[(i & 63) * 64 + (i >> 6)] = Wk[i];   // transpose Wk -> [d][e]
    }
    if (tid < 64) { bqS[tid] = bq[tid]; bkS[tid] = bk[tid]; bvS[tid] = bv[tid]; }
    __syncthreads();

    const int NPAIR = NTOK / 2;
    for (int pair = blockIdx.x * AWARPS + wid; pair < NPAIR; pair += GRID * AWARPS) {
        const int tok0 = pair * 2;
        const int b = tok0 / NN;
        const int n = tok0 - b * NN;          // even

        int to, urow;
        if (n < 4096) {                       // bunch 0: rel=2, to=4
            to = 4;
            urow = (n < 2048) ? (n * 4) : (24576 + (n - 2048) * 4);
        } else if (n < 6144) {                // bunch 1: rel=4, to=8
            int m = n - 4096;
            to = 8;
            urow = (m < 1024) ? (8192 + m * 8) : (32768 + (m - 1024) * 8);
        } else {                              // bunch 2: rel=8, to=16
            int m = n - 6144;
            to = 16;
            urow = (m < 512) ? (16384 + m * 16) : (40960 + (m - 512) * 16);
        }
        // token n+1 uses rows [urow+to, urow+2*to) -> contiguous 2*to rows

        const float* xr = x + (size_t)tok0 * 64;
        const float4* ur4 = (const float4*)(u + ((size_t)b * UU + (size_t)urow) * 64);

        // stage u tile: 2*to rows of 64 floats, padded stride 68
        const int cnt4 = 2 * to * 16;
        #pragma unroll 4
        for (int i4 = L; i4 < cnt4; i4 += 32) {
            float4 v = ur4[i4];
            *((float4*)(uS + (i4 >> 4) * 68) + (i4 & 15)) = v;
        }

        // stage x transposed: xT[ch][tok]
        {
            float2 xa = *(const float2*)(xr + 2 * L);
            float2 xb = *(const float2*)(xr + 64 + 2 * L);
            float4 st = make_float4(xa.x, xb.x, xa.y, xb.y);
            *(float4*)(xT + 4 * L) = st;
        }
        __syncwarp();

        // q = x @ Wq + bq for both tokens; lane owns ch 2L, 2L+1
        float qa0 = bqS[2 * L], qa1 = bqS[2 * L + 1];
        float qb0 = qa0,        qb1 = qa1;
        #pragma unroll 8
        for (int e = 0; e < 64; e++) {
            float2 xe = *(const float2*)(xT + 2 * e);        // (x0[e], x1[e]) bcast
            float2 w  = *(const float2*)(WqS + e * 64 + 2 * L);
            qa0 = fmaf(xe.x, w.x, qa0); qa1 = fmaf(xe.x, w.y, qa1);
            qb0 = fmaf(xe.y, w.x, qb0); qb1 = fmaf(xe.y, w.y, qb1);
        }
        *(float4*)(qS + 4 * L) = make_float4(qa0, qb0, qa1, qb1);  // qS[ch][tok]
        __syncwarp();

        // r[t][g][e] (e = L, L+32) and s[t][g]
        float s0_0, s0_1, s0_2, s0_3, s1_0, s1_1, s1_2, s1_3;
        #pragma unroll
        for (int g = 0; g < 4; g++) {
            float ra0 = 0.f, ra1 = 0.f, rb0 = 0.f, rb1 = 0.f, sa = 0.f, sb = 0.f;
            #pragma unroll
            for (int dd = 0; dd < 16; dd++) {
                const int d = g * 16 + dd;
                float2 qd = *(const float2*)(qS + 2 * d);    // (q0[d], q1[d]) bcast
                float wkl = WkTS[d * 64 + L];
                float wkh = WkTS[d * 64 + L + 32];
                float bkd = bkS[d];
                ra0 = fmaf(wkl, qd.x, ra0); ra1 = fmaf(wkh, qd.x, ra1);
                rb0 = fmaf(wkl, qd.y, rb0); rb1 = fmaf(wkh, qd.y, rb1);
                sa  = fmaf(bkd, qd.x, sa);  sb  = fmaf(bkd, qd.y, sb);
            }
            rwS[g * 68 + L]            = ra0;
            rwS[g * 68 + L + 32]       = ra1;
            rwS[272 + g * 68 + L]      = rb0;
            rwS[272 + g * 68 + L + 32] = rb1;
            if (g == 0) { s0_0 = sa; s1_0 = sb; }
            else if (g == 1) { s0_1 = sa; s1_1 = sb; }
            else if (g == 2) { s0_2 = sa; s1_2 = sb; }
            else { s0_3 = sa; s1_3 = sb; }
        }
        __syncwarp();

        // logits via FFMA2: lg[rep], rep < nrep = to/4; p = rep*32+L = t2*4+g
        const int nrep = to >> 2;
        float lg[4];
        #pragma unroll
        for (int rep = 0; rep < 4; rep++) {
            if (rep < nrep) {
                int p = rep * 32 + L;
                int t2 = p >> 2, g = p & 3;
                int tk = (t2 >= to);
                float sacc = tk ? ((g == 0) ? s1_0 : (g == 1) ? s1_1 : (g == 2) ? s1_2 : s1_3)
                                : ((g == 0) ? s0_0 : (g == 1) ? s0_1 : (g == 2) ? s0_2 : s0_3);
                const ulonglong2* up = (const ulonglong2*)(uS + t2 * 68);
                const ulonglong2* rp = (const ulonglong2*)(rwS + tk * 272 + g * 68);
                unsigned long long acc2a = 0ULL, acc2b = 0ULL;
                #pragma unroll
                for (int e4 = 0; e4 < 16; e4++) {
                    ulonglong2 a = up[e4], bb = rp[e4];
                    acc2a = ffma2(a.x, bb.x, acc2a);
                    acc2b = ffma2(a.y, bb.y, acc2b);
                }
                float2 pa = unpk2(acc2a), pb = unpk2(acc2b);
                lg[rep] = (sacc + pa.x + pa.y + pb.x + pb.y) * 0.125f;
            }
        }

        // in-register softmax over t per (token, group), butterfly shfl
        if (to == 4) {
            float m = lg[0];
            m = fmaxf(m, __shfl_xor_sync(0xffffffffu, m, 4));
            m = fmaxf(m, __shfl_xor_sync(0xffffffffu, m, 8));
            float e = expf(lg[0] - m);
            float s = e;
            s += __shfl_xor_sync(0xffffffffu, s, 4);
            s += __shfl_xor_sync(0xffffffffu, s, 8);
            atS[L] = e / s;
        } else if (to == 8) {
            #pragma unroll
            for (int rep = 0; rep < 2; rep++) {
                float m = lg[rep];
                m = fmaxf(m, __shfl_xor_sync(0xffffffffu, m, 4));
                m = fmaxf(m, __shfl_xor_sync(0xffffffffu, m, 8));
                m = fmaxf(m, __shfl_xor_sync(0xffffffffu, m, 16));
                float e = expf(lg[rep] - m);
                float s = e;
                s += __shfl_xor_sync(0xffffffffu, s, 4);
                s += __shfl_xor_sync(0xffffffffu, s, 8);
                s += __shfl_xor_sync(0xffffffffu, s, 16);
                atS[rep * 32 + L] = e / s;
            }
        } else {
            #pragma unroll
            for (int half = 0; half < 2; half++) {
                float la = lg[half * 2], lb = lg[half * 2 + 1];
                float m = fmaxf(la, lb);
                m = fmaxf(m, __shfl_xor_sync(0xffffffffu, m, 4));
                m = fmaxf(m, __shfl_xor_sync(0xffffffffu, m, 8));
                m = fmaxf(m, __shfl_xor_sync(0xffffffffu, m, 16));
                float ea = expf(la - m), eb = expf(lb - m);
                float s = ea + eb;
                s += __shfl_xor_sync(0xffffffffu, s, 4);
                s += __shfl_xor_sync(0xffffffffu, s, 8);
                s += __shfl_xor_sync(0xffffffffu, s, 16);
                float is = 1.f / s;
                atS[half * 64 + L]      = ea * is;
                atS[half * 64 + 32 + L] = eb * is;
            }
        }
        __syncwarp();

        // w[t][g][e] = sum_t attn * u ; e = L, L+32
        float wa0[4] = {0.f,0.f,0.f,0.f}, wa1[4] = {0.f,0.f,0.f,0.f};
        float wb0[4] = {0.f,0.f,0.f,0.f}, wb1[4] = {0.f,0.f,0.f,0.f};
        #pragma unroll 4
        for (int t = 0; t < to; t++) {
            float4 a0 = *(const float4*)(atS + t * 4);
            float4 a1 = *(const float4*)(atS + (to + t) * 4);
            float u00 = uS[t * 68 + L],        u01 = uS[t * 68 + L + 32];
            float u10 = uS[(to + t) * 68 + L], u11 = uS[(to + t) * 68 + L + 32];
            wa0[0] = fmaf(a0.x, u00, wa0[0]); wa1[0] = fmaf(a0.x, u01, wa1[0]);
            wa0[1] = fmaf(a0.y, u00, wa0[1]); wa1[1] = fmaf(a0.y, u01, wa1[1]);
            wa0[2] = fmaf(a0.z, u00, wa0[2]); wa1[2] = fmaf(a0.z, u01, wa1[2]);
            wa0[3] = fmaf(a0.w, u00, wa0[3]); wa1[3] = fmaf(a0.w, u01, wa1[3]);
            wb0[0] = fmaf(a1.x, u10, wb0[0]); wb1[0] = fmaf(a1.x, u11, wb1[0]);
            wb0[1] = fmaf(a1.y, u10, wb0[1]); wb1[1] = fmaf(a1.y, u11, wb1[1]);
            wb0[2] = fmaf(a1.z, u10, wb0[2]); wb1[2] = fmaf(a1.z, u11, wb1[2]);
            wb0[3] = fmaf(a1.w, u10, wb0[3]); wb1[3] = fmaf(a1.w, u11, wb1[3]);
        }
        __syncwarp();   // logits reads of rwS done; safe to overwrite with w
        #pragma unroll
        for (int g = 0; g < 4; g++) {
            rwS[g * 68 + L]            = wa0[g];
            rwS[g * 68 + L + 32]       = wa1[g];
            rwS[272 + g * 68 + L]      = wb0[g];
            rwS[272 + g * 68 + L + 32] = wb1[g];
        }
        __syncwarp();

        // out[c] = w[g(c)] . Wv[:,c] + bv[c] ; lane owns ch 2L, 2L+1 (same group)
        {
            const int g = L >> 3;     // group of channel 2L (= (2L)>>4)
            const float* w0 = rwS + g * 68;
            const float* w1 = rwS + 272 + g * 68;
            float oa0 = bvS[2 * L], oa1 = bvS[2 * L + 1];
            float ob0 = oa0,        ob1 = oa1;
            #pragma unroll 8
            for (int e = 0; e < 64; e++) {
                float2 wv = *(const float2*)(WvS + e * 64 + 2 * L);
                float we0 = w0[e], we1 = w1[e];
                oa0 = fmaf(we0, wv.x, oa0); oa1 = fmaf(we0, wv.y, oa1);
                ob0 = fmaf(we1, wv.x, ob0); ob1 = fmaf(we1, wv.y, ob1);
            }
            *(float2*)(g_z + (size_t)tok0 * 64 + 2 * L)       = make_float2(oa0, oa1);
            *(float2*)(g_z + (size_t)(tok0 + 1) * 64 + 2 * L) = make_float2(ob0, ob1);
        }
        __syncwarp();   // protect per-warp tiles before next iteration
    }
}

// ===========================================================================
// Kernel B: LN1 -> MLP (exact gelu) -> LN2 -> + shortcut(x@Ws+bs)
// 4 tokens/warp, 14 warps.  GEMM loops use FFMA2 packed over token pairs
// (znT/hT/xT tiles are [ch][tok] so token pairs are 64-bit adjacent).
// smem: weights 37504 | per warp (14): znT 256 | xT 256 | hT 512 (=1024)
// total = 37504 + 14*1024 = 51840 floats = 207360 B
// ===========================================================================
#define MTHREADS 448
#define MWARPS 14

__device__ __forceinline__ int hswz(int e) {   // conflict-free slot for hT
    return (e ^ ((e >> 3) & 3)) * 4;
}

__device__ __forceinline__ float gelu1(float v) {
    return 0.5f * v * (1.f + erff(v * 0.70710678118654752f));
}

__global__ __launch_bounds__(MTHREADS, 1)
void mlp_kernel(const float* __restrict__ x,
                const float* __restrict__ g1, const float* __restrict__ be1,
                const float* __restrict__ Wm1, const float* __restrict__ bm1,
                const float* __restrict__ Wm2, const float* __restrict__ bm2,
                const float* __restrict__ g2, const float* __restrict__ be2,
                const float* __restrict__ Ws, const float* __restrict__ bs,
                float* __restrict__ out)
{
    extern __shared__ float sm[];
    float* W1S  = sm;            // [e][256]
    float* W2S  = sm + 16384;    // [e][64]
    float* WsS  = sm + 32768;    // [e][64]
    float* bm1S = sm + 36864;
    float* bm2S = sm + 37120;
    float* bsS  = sm + 37184;
    float* g1S  = sm + 37248;
    float* be1S = sm + 37312;
    float* g2S  = sm + 37376;
    float* be2S = sm + 37440;

    const int tid = threadIdx.x;
    const int wid = tid >> 5;
    const int L   = tid & 31;

    float* wbase = sm + 37504 + wid * 1024;
    float* znT = wbase;          // [ch][4]
    float* xT  = wbase + 256;    // [ch][4]
    float* hT  = wbase + 512;    // 128 x 4, swizzled

    for (int i = tid; i < 16384; i += MTHREADS) { W1S[i] = Wm1[i]; W2S[i] = Wm2[i]; }
    for (int i = tid; i < 4096;  i += MTHREADS) WsS[i] = Ws[i];
    if (tid < 256) bm1S[tid] = bm1[tid];
    if (tid < 64) {
        bm2S[tid] = bm2[tid]; bsS[tid] = bs[tid];
        g1S[tid] = g1[tid];   be1S[tid] = be1[tid];
        g2S[tid] = g2[tid];   be2S[tid] = be2[tid];
    }
    __syncthreads();

    const int NGRP = NTOK / 4;
    for (int grp = blockIdx.x * MWARPS + wid; grp < NGRP; grp += GRID * MWARPS) {
        const int tok0 = grp * 4;
        const size_t base = (size_t)tok0 * 64;

        // ---- LN1 on 4 tokens (lane owns ch L, L+32); one-pass form ----
        float zn0[4], zn1[4];
        #pragma unroll
        for (int t = 0; t < 4; t++) {
            float z0 = g_z[base + t * 64 + L];
            float z1 = g_z[base + t * 64 + L + 32];
            float s1 = warpSum(z0 + z1);
            float s2 = warpSum(fmaf(z0, z0, z1 * z1));
            float mean = s1 * (1.f / 64.f);
            float var  = fmaf(-mean, mean, s2 * (1.f / 64.f));
            float inv = rsqrtf(var + 1e-5f);
            zn0[t] = (z0 - mean) * inv * g1S[L]      + be1S[L];
            zn1[t] = (z1 - mean) * inv * g1S[L + 32] + be1S[L + 32];
        }
        *(float4*)(znT + 4 * L)        = make_float4(zn0[0], zn0[1], zn0[2], zn0[3]);
        *(float4*)(znT + 4 * (L + 32)) = make_float4(zn1[0], zn1[1], zn1[2], zn1[3]);

        // stage x transposed for the shortcut
        {
            float xa[4], xb[4];
            #pragma unroll
            for (int t = 0; t < 4; t++) {
                xa[t] = x[base + t * 64 + L];
                xb[t] = x[base + t * 64 + L + 32];
            }
            *(float4*)(xT + 4 * L)        = make_float4(xa[0], xa[1], xa[2], xa[3]);
            *(float4*)(xT + 4 * (L + 32)) = make_float4(xb[0], xb[1], xb[2], xb[3]);
        }
        __syncwarp();

        // ---- h = zn @ Wm1 + bm1 ; packed (tok0,tok1),(tok2,tok3) per channel
        unsigned long long h2[8][2];
        {
            float4 bA = *(const float4*)(bm1S + 4 * L);
            float4 bB = *(const float4*)(bm1S + 128 + 4 * L);
            h2[0][0] = h2[0][1] = dup2(bA.x);
            h2[1][0] = h2[1][1] = dup2(bA.y);
            h2[2][0] = h2[2][1] = dup2(bA.z);
            h2[3][0] = h2[3][1] = dup2(bA.w);
            h2[4][0] = h2[4][1] = dup2(bB.x);
            h2[5][0] = h2[5][1] = dup2(bB.y);
            h2[6][0] = h2[6][1] = dup2(bB.z);
            h2[7][0] = h2[7][1] = dup2(bB.w);
        }
        #pragma unroll 4
        for (int e = 0; e < 64; e++) {
            ulonglong2 zn2 = *(const ulonglong2*)(znT + 4 * e);
            float4 wA = *(const float4*)(W1S + e * 256 + 4 * L);
            float4 wB = *(const float4*)(W1S + e * 256 + 128 + 4 * L);
            unsigned long long d;
            d = dup2(wA.x); h2[0][0] = ffma2(zn2.x, d, h2[0][0]); h2[0][1] = ffma2(zn2.y, d, h2[0][1]);
            d = dup2(wA.y); h2[1][0] = ffma2(zn2.x, d, h2[1][0]); h2[1][1] = ffma2(zn2.y, d, h2[1][1]);
            d = dup2(wA.z); h2[2][0] = ffma2(zn2.x, d, h2[2][0]); h2[2][1] = ffma2(zn2.y, d, h2[2][1]);
            d = dup2(wA.w); h2[3][0] = ffma2(zn2.x, d, h2[3][0]); h2[3][1] = ffma2(zn2.y, d, h2[3][1]);
            d = dup2(wB.x); h2[4][0] = ffma2(zn2.x, d, h2[4][0]); h2[4][1] = ffma2(zn2.y, d, h2[4][1]);
            d = dup2(wB.y); h2[5][0] = ffma2(zn2.x, d, h2[5][0]); h2[5][1] = ffma2(zn2.y, d, h2[5][1]);
            d = dup2(wB.z); h2[6][0] = ffma2(zn2.x, d, h2[6][0]); h2[6][1] = ffma2(zn2.y, d, h2[6][1]);
            d = dup2(wB.w); h2[7][0] = ffma2(zn2.x, d, h2[7][0]); h2[7][1] = ffma2(zn2.y, d, h2[7][1]);
        }

        // unpack + exact gelu -> hv[j][t]
        float hv[8][4];
        #pragma unroll
        for (int j = 0; j < 8; j++) {
            float2 p0 = unpk2(h2[j][0]);
            float2 p1 = unpk2(h2[j][1]);
            hv[j][0] = gelu1(p0.x); hv[j][1] = gelu1(p0.y);
            hv[j][2] = gelu1(p1.x); hv[j][3] = gelu1(p1.y);
        }

        // ---- o = h @ Wm2 + bm2 ; packed accumulators over token pairs ----
        unsigned long long o01x, o23x, o01y, o23y;
        {
            float2 b2 = *(const float2*)(bm2S + 2 * L);
            o01x = o23x = dup2(b2.x);
            o01y = o23y = dup2(b2.y);
        }
        // half 0: channels e in [0,128)
        #pragma unroll
        for (int j = 0; j < 4; j++)
            *(float4*)(hT + hswz(4 * L + j)) = make_float4(hv[j][0], hv[j][1], hv[j][2], hv[j][3]);
        __syncwarp();
        #pragma unroll 4
        for (int e = 0; e < 128; e++) {
            ulonglong2 hp = *(const ulonglong2*)(hT + hswz(e));
            float2 w2 = *(const float2*)(W2S + e * 64 + 2 * L);
            unsigned long long wx = dup2(w2.x), wy = dup2(w2.y);
            o01x = ffma2(hp.x, wx, o01x); o23x = ffma2(hp.y, wx, o23x);
            o01y = ffma2(hp.x, wy, o01y); o23y = ffma2(hp.y, wy, o23y);
        }
        __syncwarp();
        // half 1: channels e in [128,256)
        #pragma unroll
        for (int j = 0; j < 4; j++)
            *(float4*)(hT + hswz(4 * L + j)) = make_float4(hv[4+j][0], hv[4+j][1], hv[4+j][2], hv[4+j][3]);
        __syncwarp();
        #pragma unroll 4
        for (int e = 0; e < 128; e++) {
            ulonglong2 hp = *(const ulonglong2*)(hT + hswz(e));
            float2 w2 = *(const float2*)(W2S + (e + 128) * 64 + 2 * L);
            unsigned long long wx = dup2(w2.x), wy = dup2(w2.y);
            o01x = ffma2(hp.x, wx, o01x); o23x = ffma2(hp.y, wx, o23x);
            o01y = ffma2(hp.x, wy, o01y); o23y = ffma2(hp.y, wy, o23y);
        }

        // ---- shortcut = x @ Ws + bs ; packed ----
        unsigned long long s01x, s23x, s01y, s23y;
        {
            float2 b2 = *(const float2*)(bsS + 2 * L);
            s01x = s23x = dup2(b2.x);
            s01y = s23y = dup2(b2.y);
        }
        #pragma unroll 4
        for (int e = 0; e < 64; e++) {
            ulonglong2 xp = *(const ulonglong2*)(xT + 4 * e);
            float2 ws = *(const float2*)(WsS + e * 64 + 2 * L);
            unsigned long long wx = dup2(ws.x), wy = dup2(ws.y);
            s01x = ffma2(xp.x, wx, s01x); s23x = ffma2(xp.y, wx, s23x);
            s01y = ffma2(xp.x, wy, s01y); s23y = ffma2(xp.y, wy, s23y);
        }

        // unpack accumulators
        float o0[4], o1[4], sc0[4], sc1[4];
        {
            float2 a = unpk2(o01x), bq_ = unpk2(o23x);
            o0[0] = a.x; o0[1] = a.y; o0[2] = bq_.x; o0[3] = bq_.y;
            float2 c = unpk2(o01y), d = unpk2(o23y);
            o1[0] = c.x; o1[1] = c.y; o1[2] = d.x; o1[3] = d.y;
            float2 e_ = unpk2(s01x), f = unpk2(s23x);
            sc0[0] = e_.x; sc0[1] = e_.y; sc0[2] = f.x; sc0[3] = f.y;
            float2 g_ = unpk2(s01y), h_ = unpk2(s23y);
            sc1[0] = g_.x; sc1[1] = g_.y; sc1[2] = h_.x; sc1[3] = h_.y;
        }

        // ---- LN2 (one-pass) + add shortcut, store ----
        #pragma unroll
        for (int t = 0; t < 4; t++) {
            float s1 = warpSum(o0[t] + o1[t]);
            float s2 = warpSum(fmaf(o0[t], o0[t], o1[t] * o1[t]));
            float m2 = s1 * (1.f / 64.f);
            float v2 = fmaf(-m2, m2, s2 * (1.f / 64.f));
            float inv2 = rsqrtf(v2 + 1e-5f);
            float on0 = (o0[t] - m2) * inv2 * g2S[2 * L]     + be2S[2 * L];
            float on1 = (o1[t] - m2) * inv2 * g2S[2 * L + 1] + be2S[2 * L + 1];
            *(float2*)(out + base + t * 64 + 2 * L) = make_float2(on0 + sc0[t], on1 + sc1[t]);
        }
        __syncwarp();   // protect tiles before next group
    }
}

// ===========================================================================
extern "C" void kernel_launch(void* const* d_in, const int* in_sizes, int n_in,
                              void* d_out, int out_size)
{
    const float* u   = (const float*)d_in[0];
    const float* x   = (const float*)d_in[1];
    const float* Wk  = (const float*)d_in[2];
    const float* bk  = (const float*)d_in[3];
    const float* Wq  = (const float*)d_in[4];
    const float* bq  = (const float*)d_in[5];
    const float* Wv  = (const float*)d_in[6];
    const float* bv  = (const float*)d_in[7];
    const float* g1  = (const float*)d_in[8];
    const float* be1 = (const float*)d_in[9];
    const float* Wm1 = (const float*)d_in[10];
    const float* bm1 = (const float*)d_in[11];
    const float* Wm2 = (const float*)d_in[12];
    const float* bm2 = (const float*)d_in[13];
    const float* g2  = (const float*)d_in[14];
    const float* be2 = (const float*)d_in[15];
    const float* Ws  = (const float*)d_in[16];
    const float* bs  = (const float*)d_in[17];
    float* out = (float*)d_out;

    const int smemA = 55936 * 4;   // 223744 B
    const int smemB = 51840 * 4;   // 207360 B
    cudaFuncSetAttribute(attn_kernel, cudaFuncAttributeMaxDynamicSharedMemorySize, smemA);
    cudaFuncSetAttribute(mlp_kernel,  cudaFuncAttributeMaxDynamicSharedMemorySize, smemB);

    attn_kernel<<<GRID, ATHREADS, smemA>>>(u, x, Wk, bk, Wq, bq, Wv, bv);
    mlp_kernel<<<GRID, MTHREADS, smemB>>>(x, g1, be1, Wm1, bm1, Wm2, bm2,
                                          g2, be2, Ws, bs, out);
}

// round 17
// speedup vs baseline: 2.0831x; 1.0082x over previous
#include <cuda_runtime.h>
#include <math.h>

// Problem constants
#define BB 8
#define NN 7168
#define NTOK (BB*NN)            // 57344
#define UU 49152
#define GRID 148

__device__ float g_z[(size_t)NTOK * 64];   // attention output scratch (pre-LN)

__device__ __forceinline__ float warpSum(float v) {
    v += __shfl_xor_sync(0xffffffffu, v, 16);
    v += __shfl_xor_sync(0xffffffffu, v, 8);
    v += __shfl_xor_sync(0xffffffffu, v, 4);
    v += __shfl_xor_sync(0xffffffffu, v, 2);
    v += __shfl_xor_sync(0xffffffffu, v, 1);
    return v;
}

// ---- packed f32x2 helpers (FFMA2: 2 fp32 FMAs per instruction) ----
__device__ __forceinline__ unsigned long long dup2(float v) {
    unsigned long long r;
    unsigned int b = __float_as_uint(v);
    asm("mov.b64 %0, {%1, %2};" : "=l"(r) : "r"(b), "r"(b));
    return r;
}
__device__ __forceinline__ unsigned long long ffma2(unsigned long long a,
                                                    unsigned long long b,
                                                    unsigned long long c) {
    unsigned long long d;
    asm("fma.rn.f32x2 %0, %1, %2, %3;" : "=l"(d) : "l"(a), "l"(b), "l"(c));
    return d;
}
__device__ __forceinline__ float2 unpk2(unsigned long long v) {
    unsigned int lo, hi;
    asm("mov.b64 {%0, %1}, %2;" : "=r"(lo), "=r"(hi) : "l"(v));
    return make_float2(__uint_as_float(lo), __uint_as_float(hi));
}

// ===========================================================================
// Kernel A: bunched grouped cross-attention -> g_z.  Token-PAIR per warp.
// Butterfly softmax; ALL matvec loops now FFMA2-packed.
// total smem = 12480 + 14*3104 = 55936 floats = 223744 B
// ===========================================================================
#define ATHREADS 448
#define AWARPS 14

__global__ __launch_bounds__(ATHREADS, 1)
void attn_kernel(const float* __restrict__ u, const float* __restrict__ x,
                 const float* __restrict__ Wk, const float* __restrict__ bk,
                 const float* __restrict__ Wq, const float* __restrict__ bq,
                 const float* __restrict__ Wv, const float* __restrict__ bv)
{
    extern __shared__ float sm[];
    float* WqS  = sm;
    float* WkTS = sm + 4096;
    float* WvS  = sm + 8192;
    float* bqS  = sm + 12288;
    float* bkS  = sm + 12352;
    float* bvS  = sm + 12416;

    const int tid = threadIdx.x;
    const int wid = tid >> 5;
    const int L   = tid & 31;

    float* warpS = sm + 12480 + wid * 3104;
    float* uS  = warpS;          // 32 x 68
    float* rwS = warpS + 2176;   // 2 tokens x 4 x 68 (r, later w)
    float* qS  = warpS + 2720;   // [ch][tok] 64 x 2
    float* xT  = warpS + 2848;   // [ch][tok] 64 x 2
    float* atS = warpS + 2976;   // 128 attn

    for (int i = tid; i < 4096; i += ATHREADS) {
        WqS[i] = Wq[i];
        WvS[i] = Wv[i];
        WkTS[(i & 63) * 64 + (i >> 6)] = Wk[i];   // transpose Wk -> [d][e]
    }
    if (tid < 64) { bqS[tid] = bq[tid]; bkS[tid] = bk[tid]; bvS[tid] = bv[tid]; }
    __syncthreads();

    const int NPAIR = NTOK / 2;
    for (int pair = blockIdx.x * AWARPS + wid; pair < NPAIR; pair += GRID * AWARPS) {
        const int tok0 = pair * 2;
        const int b = tok0 / NN;
        const int n = tok0 - b * NN;          // even

        int to, urow;
        if (n < 4096) {                       // bunch 0: rel=2, to=4
            to = 4;
            urow = (n < 2048) ? (n * 4) : (24576 + (n - 2048) * 4);
        } else if (n < 6144) {                // bunch 1: rel=4, to=8
            int m = n - 4096;
            to = 8;
            urow = (m < 1024) ? (8192 + m * 8) : (32768 + (m - 1024) * 8);
        } else {                              // bunch 2: rel=8, to=16
            int m = n - 6144;
            to = 16;
            urow = (m < 512) ? (16384 + m * 16) : (40960 + (m - 512) * 16);
        }
        // token n+1 uses rows [urow+to, urow+2*to) -> contiguous 2*to rows

        const float* xr = x + (size_t)tok0 * 64;
        const float4* ur4 = (const float4*)(u + ((size_t)b * UU + (size_t)urow) * 64);

        // stage u tile: 2*to rows of 64 floats, padded stride 68
        const int cnt4 = 2 * to * 16;
        #pragma unroll 4
        for (int i4 = L; i4 < cnt4; i4 += 32) {
            float4 v = ur4[i4];
            *((float4*)(uS + (i4 >> 4) * 68) + (i4 & 15)) = v;
        }

        // stage x transposed: xT[ch][tok]
        {
            float2 xa = *(const float2*)(xr + 2 * L);
            float2 xb = *(const float2*)(xr + 64 + 2 * L);
            float4 st = make_float4(xa.x, xb.x, xa.y, xb.y);
            *(float4*)(xT + 4 * L) = st;
        }
        __syncwarp();

        // q = x @ Wq + bq, packed over ch pair (2L, 2L+1)
        unsigned long long qa2 = *(const unsigned long long*)(bqS + 2 * L);
        unsigned long long qb2 = qa2;
        #pragma unroll 8
        for (int e = 0; e < 64; e++) {
            float2 xe = *(const float2*)(xT + 2 * e);        // (x0[e], x1[e]) bcast
            unsigned long long w2 = *(const unsigned long long*)(WqS + e * 64 + 2 * L);
            qa2 = ffma2(w2, dup2(xe.x), qa2);
            qb2 = ffma2(w2, dup2(xe.y), qb2);
        }
        {
            float2 pa = unpk2(qa2), pb = unpk2(qb2);
            *(float4*)(qS + 4 * L) = make_float4(pa.x, pb.x, pa.y, pb.y);  // qS[ch][tok]
        }
        __syncwarp();

        // r[t][g][e] and s[t][g], packed over token pair
        float s0_0, s0_1, s0_2, s0_3, s1_0, s1_1, s1_2, s1_3;
        #pragma unroll
        for (int g = 0; g < 4; g++) {
            unsigned long long r0 = 0ULL, r1 = 0ULL, ss = 0ULL;
            #pragma unroll
            for (int dd = 0; dd < 16; dd++) {
                const int d = g * 16 + dd;
                unsigned long long qd2 = *(const unsigned long long*)(qS + 2 * d); // (q0,q1)
                r0 = ffma2(qd2, dup2(WkTS[d * 64 + L]), r0);
                r1 = ffma2(qd2, dup2(WkTS[d * 64 + L + 32]), r1);
                ss = ffma2(qd2, dup2(bkS[d]), ss);
            }
            float2 p0 = unpk2(r0), p1 = unpk2(r1), ps = unpk2(ss);
            rwS[g * 68 + L]            = p0.x;
            rwS[g * 68 + L + 32]       = p1.x;
            rwS[272 + g * 68 + L]      = p0.y;
            rwS[272 + g * 68 + L + 32] = p1.y;
            if (g == 0) { s0_0 = ps.x; s1_0 = ps.y; }
            else if (g == 1) { s0_1 = ps.x; s1_1 = ps.y; }
            else if (g == 2) { s0_2 = ps.x; s1_2 = ps.y; }
            else { s0_3 = ps.x; s1_3 = ps.y; }
        }
        __syncwarp();

        // logits via FFMA2: lg[rep], rep < nrep = to/4; p = rep*32+L = t2*4+g
        const int nrep = to >> 2;
        float lg[4];
        #pragma unroll
        for (int rep = 0; rep < 4; rep++) {
            if (rep < nrep) {
                int p = rep * 32 + L;
                int t2 = p >> 2, g = p & 3;
                int tk = (t2 >= to);
                float sacc = tk ? ((g == 0) ? s1_0 : (g == 1) ? s1_1 : (g == 2) ? s1_2 : s1_3)
                                : ((g == 0) ? s0_0 : (g == 1) ? s0_1 : (g == 2) ? s0_2 : s0_3);
                const ulonglong2* up = (const ulonglong2*)(uS + t2 * 68);
                const ulonglong2* rp = (const ulonglong2*)(rwS + tk * 272 + g * 68);
                unsigned long long acc2a = 0ULL, acc2b = 0ULL;
                #pragma unroll
                for (int e4 = 0; e4 < 16; e4++) {
                    ulonglong2 a = up[e4], bb = rp[e4];
                    acc2a = ffma2(a.x, bb.x, acc2a);
                    acc2b = ffma2(a.y, bb.y, acc2b);
                }
                float2 pa = unpk2(acc2a), pb = unpk2(acc2b);
                lg[rep] = (sacc + pa.x + pa.y + pb.x + pb.y) * 0.125f;
            }
        }

        // in-register softmax over t per (token, group), butterfly shfl
        if (to == 4) {
            float m = lg[0];
            m = fmaxf(m, __shfl_xor_sync(0xffffffffu, m, 4));
            m = fmaxf(m, __shfl_xor_sync(0xffffffffu, m, 8));
            float e = expf(lg[0] - m);
            float s = e;
            s += __shfl_xor_sync(0xffffffffu, s, 4);
            s += __shfl_xor_sync(0xffffffffu, s, 8);
            atS[L] = e / s;
        } else if (to == 8) {
            #pragma unroll
            for (int rep = 0; rep < 2; rep++) {
                float m = lg[rep];
                m = fmaxf(m, __shfl_xor_sync(0xffffffffu, m, 4));
                m = fmaxf(m, __shfl_xor_sync(0xffffffffu, m, 8));
                m = fmaxf(m, __shfl_xor_sync(0xffffffffu, m, 16));
                float e = expf(lg[rep] - m);
                float s = e;
                s += __shfl_xor_sync(0xffffffffu, s, 4);
                s += __shfl_xor_sync(0xffffffffu, s, 8);
                s += __shfl_xor_sync(0xffffffffu, s, 16);
                atS[rep * 32 + L] = e / s;
            }
        } else {
            #pragma unroll
            for (int half = 0; half < 2; half++) {
                float la = lg[half * 2], lb = lg[half * 2 + 1];
                float m = fmaxf(la, lb);
                m = fmaxf(m, __shfl_xor_sync(0xffffffffu, m, 4));
                m = fmaxf(m, __shfl_xor_sync(0xffffffffu, m, 8));
                m = fmaxf(m, __shfl_xor_sync(0xffffffffu, m, 16));
                float ea = expf(la - m), eb = expf(lb - m);
                float s = ea + eb;
                s += __shfl_xor_sync(0xffffffffu, s, 4);
                s += __shfl_xor_sync(0xffffffffu, s, 8);
                s += __shfl_xor_sync(0xffffffffu, s, 16);
                float is = 1.f / s;
                atS[half * 64 + L]      = ea * is;
                atS[half * 64 + 32 + L] = eb * is;
            }
        }
        __syncwarp();

        // w[t][g][e] = sum_t attn * u ; packed over adjacent g pairs
        unsigned long long wa0p[2] = {0ULL, 0ULL}, wa1p[2] = {0ULL, 0ULL};
        unsigned long long wb0p[2] = {0ULL, 0ULL}, wb1p[2] = {0ULL, 0ULL};
        #pragma unroll 4
        for (int t = 0; t < to; t++) {
            ulonglong2 a0p = *(const ulonglong2*)(atS + t * 4);        // (g0,g1),(g2,g3)
            ulonglong2 a1p = *(const ulonglong2*)(atS + (to + t) * 4);
            unsigned long long du00 = dup2(uS[t * 68 + L]);
            unsigned long long du01 = dup2(uS[t * 68 + L + 32]);
            unsigned long long du10 = dup2(uS[(to + t) * 68 + L]);
            unsigned long long du11 = dup2(uS[(to + t) * 68 + L + 32]);
            wa0p[0] = ffma2(a0p.x, du00, wa0p[0]); wa0p[1] = ffma2(a0p.y, du00, wa0p[1]);
            wa1p[0] = ffma2(a0p.x, du01, wa1p[0]); wa1p[1] = ffma2(a0p.y, du01, wa1p[1]);
            wb0p[0] = ffma2(a1p.x, du10, wb0p[0]); wb0p[1] = ffma2(a1p.y, du10, wb0p[1]);
            wb1p[0] = ffma2(a1p.x, du11, wb1p[0]); wb1p[1] = ffma2(a1p.y, du11, wb1p[1]);
        }
        __syncwarp();   // logits reads of rwS done; safe to overwrite with w
        #pragma unroll
        for (int gp = 0; gp < 2; gp++) {
            float2 va0 = unpk2(wa0p[gp]), va1 = unpk2(wa1p[gp]);
            float2 vb0 = unpk2(wb0p[gp]), vb1 = unpk2(wb1p[gp]);
            rwS[(2 * gp) * 68 + L]            = va0.x;
            rwS[(2 * gp + 1) * 68 + L]        = va0.y;
            rwS[(2 * gp) * 68 + L + 32]       = va1.x;
            rwS[(2 * gp + 1) * 68 + L + 32]   = va1.y;
            rwS[272 + (2 * gp) * 68 + L]          = vb0.x;
            rwS[272 + (2 * gp + 1) * 68 + L]      = vb0.y;
            rwS[272 + (2 * gp) * 68 + L + 32]     = vb1.x;
            rwS[272 + (2 * gp + 1) * 68 + L + 32] = vb1.y;
        }
        __syncwarp();

        // out[c] = w[g(c)] . Wv[:,c] + bv[c] ; packed over ch pair (2L, 2L+1)
        {
            const int g = L >> 3;     // group of channel 2L
            const float* w0 = rwS + g * 68;
            const float* w1 = rwS + 272 + g * 68;
            unsigned long long oa2 = *(const unsigned long long*)(bvS + 2 * L);
            unsigned long long ob2 = oa2;
            #pragma unroll 8
            for (int e = 0; e < 64; e++) {
                unsigned long long wv2 = *(const unsigned long long*)(WvS + e * 64 + 2 * L);
                oa2 = ffma2(wv2, dup2(w0[e]), oa2);
                ob2 = ffma2(wv2, dup2(w1[e]), ob2);
            }
            float2 oa = unpk2(oa2), ob = unpk2(ob2);
            *(float2*)(g_z + (size_t)tok0 * 64 + 2 * L)       = oa;
            *(float2*)(g_z + (size_t)(tok0 + 1) * 64 + 2 * L) = ob;
        }
        __syncwarp();   // protect per-warp tiles before next iteration
    }
}

// ===========================================================================
// Kernel B: LN1 -> MLP (exact gelu) -> LN2 -> + shortcut(x@Ws+bs)
// 4 tokens/warp, 14 warps.  Wm1 packed over CHANNEL pairs (weights load
// directly as packed u64 -> only 4 zn dups/iter). Wm2/shortcut token-packed.
// smem: weights 37504 | per warp (14): znT 256 | xT 256 | hT 512 (=1024)
// total = 37504 + 14*1024 = 51840 floats = 207360 B
// ===========================================================================
#define MTHREADS 448
#define MWARPS 14

__device__ __forceinline__ int hswz(int e) {   // conflict-free slot for hT
    return (e ^ ((e >> 3) & 3)) * 4;
}

__device__ __forceinline__ float gelu1(float v) {
    return 0.5f * v * (1.f + erff(v * 0.70710678118654752f));
}

__global__ __launch_bounds__(MTHREADS, 1)
void mlp_kernel(const float* __restrict__ x,
                const float* __restrict__ g1, const float* __restrict__ be1,
                const float* __restrict__ Wm1, const float* __restrict__ bm1,
                const float* __restrict__ Wm2, const float* __restrict__ bm2,
                const float* __restrict__ g2, const float* __restrict__ be2,
                const float* __restrict__ Ws, const float* __restrict__ bs,
                float* __restrict__ out)
{
    extern __shared__ float sm[];
    float* W1S  = sm;            // [e][256]
    float* W2S  = sm + 16384;    // [e][64]
    float* WsS  = sm + 32768;    // [e][64]
    float* bm1S = sm + 36864;
    float* bm2S = sm + 37120;
    float* bsS  = sm + 37184;
    float* g1S  = sm + 37248;
    float* be1S = sm + 37312;
    float* g2S  = sm + 37376;
    float* be2S = sm + 37440;

    const int tid = threadIdx.x;
    const int wid = tid >> 5;
    const int L   = tid & 31;

    float* wbase = sm + 37504 + wid * 1024;
    float* znT = wbase;          // [ch][4]
    float* xT  = wbase + 256;    // [ch][4]
    float* hT  = wbase + 512;    // 128 x 4, swizzled

    for (int i = tid; i < 16384; i += MTHREADS) { W1S[i] = Wm1[i]; W2S[i] = Wm2[i]; }
    for (int i = tid; i < 4096;  i += MTHREADS) WsS[i] = Ws[i];
    if (tid < 256) bm1S[tid] = bm1[tid];
    if (tid < 64) {
        bm2S[tid] = bm2[tid]; bsS[tid] = bs[tid];
        g1S[tid] = g1[tid];   be1S[tid] = be1[tid];
        g2S[tid] = g2[tid];   be2S[tid] = be2[tid];
    }
    __syncthreads();

    const int NGRP = NTOK / 4;
    for (int grp = blockIdx.x * MWARPS + wid; grp < NGRP; grp += GRID * MWARPS) {
        const int tok0 = grp * 4;
        const size_t base = (size_t)tok0 * 64;

        // ---- LN1 on 4 tokens (lane owns ch L, L+32); one-pass form ----
        float zn0[4], zn1[4];
        #pragma unroll
        for (int t = 0; t < 4; t++) {
            float z0 = g_z[base + t * 64 + L];
            float z1 = g_z[base + t * 64 + L + 32];
            float s1 = warpSum(z0 + z1);
            float s2 = warpSum(fmaf(z0, z0, z1 * z1));
            float mean = s1 * (1.f / 64.f);
            float var  = fmaf(-mean, mean, s2 * (1.f / 64.f));
            float inv = rsqrtf(var + 1e-5f);
            zn0[t] = (z0 - mean) * inv * g1S[L]      + be1S[L];
            zn1[t] = (z1 - mean) * inv * g1S[L + 32] + be1S[L + 32];
        }
        *(float4*)(znT + 4 * L)        = make_float4(zn0[0], zn0[1], zn0[2], zn0[3]);
        *(float4*)(znT + 4 * (L + 32)) = make_float4(zn1[0], zn1[1], zn1[2], zn1[3]);

        // stage x transposed for the shortcut
        {
            float xa[4], xb[4];
            #pragma unroll
            for (int t = 0; t < 4; t++) {
                xa[t] = x[base + t * 64 + L];
                xb[t] = x[base + t * 64 + L + 32];
            }
            *(float4*)(xT + 4 * L)        = make_float4(xa[0], xa[1], xa[2], xa[3]);
            *(float4*)(xT + 4 * (L + 32)) = make_float4(xb[0], xb[1], xb[2], xb[3]);
        }
        __syncwarp();

        // ---- h = zn @ Wm1 + bm1 ; packed over CHANNEL pairs, 4 tokens ----
        // a2[p][t]: p=0 -> ch(4L,4L+1), p=1 -> ch(4L+2,4L+3),
        //           p=2 -> ch(128+4L, +1), p=3 -> ch(128+4L+2, +3)
        unsigned long long a2[4][4];
        {
            unsigned long long bA01 = *(const unsigned long long*)(bm1S + 4 * L);
            unsigned long long bA23 = *(const unsigned long long*)(bm1S + 4 * L + 2);
            unsigned long long bB01 = *(const unsigned long long*)(bm1S + 128 + 4 * L);
            unsigned long long bB23 = *(const unsigned long long*)(bm1S + 128 + 4 * L + 2);
            #pragma unroll
            for (int t = 0; t < 4; t++) {
                a2[0][t] = bA01; a2[1][t] = bA23; a2[2][t] = bB01; a2[3][t] = bB23;
            }
        }
        #pragma unroll 4
        for (int e = 0; e < 64; e++) {
            float4 zn4 = *(const float4*)(znT + 4 * e);      // 4 tokens, bcast
            ulonglong2 wAp = *(const ulonglong2*)(W1S + e * 256 + 4 * L);
            ulonglong2 wBp = *(const ulonglong2*)(W1S + e * 256 + 128 + 4 * L);
            unsigned long long z0 = dup2(zn4.x), z1 = dup2(zn4.y);
            unsigned long long z2 = dup2(zn4.z), z3 = dup2(zn4.w);
            a2[0][0] = ffma2(wAp.x, z0, a2[0][0]); a2[0][1] = ffma2(wAp.x, z1, a2[0][1]);
            a2[0][2] = ffma2(wAp.x, z2, a2[0][2]); a2[0][3] = ffma2(wAp.x, z3, a2[0][3]);
            a2[1][0] = ffma2(wAp.y, z0, a2[1][0]); a2[1][1] = ffma2(wAp.y, z1, a2[1][1]);
            a2[1][2] = ffma2(wAp.y, z2, a2[1][2]); a2[1][3] = ffma2(wAp.y, z3, a2[1][3]);
            a2[2][0] = ffma2(wBp.x, z0, a2[2][0]); a2[2][1] = ffma2(wBp.x, z1, a2[2][1]);
            a2[2][2] = ffma2(wBp.x, z2, a2[2][2]); a2[2][3] = ffma2(wBp.x, z3, a2[2][3]);
            a2[3][0] = ffma2(wBp.y, z0, a2[3][0]); a2[3][1] = ffma2(wBp.y, z1, a2[3][1]);
            a2[3][2] = ffma2(wBp.y, z2, a2[3][2]); a2[3][3] = ffma2(wBp.y, z3, a2[3][3]);
        }

        // unpack + exact gelu -> hv[j][t]
        float hv[8][4];
        #pragma unroll
        for (int p = 0; p < 4; p++) {
            #pragma unroll
            for (int t = 0; t < 4; t++) {
                float2 v = unpk2(a2[p][t]);
                hv[2 * p][t]     = gelu1(v.x);
                hv[2 * p + 1][t] = gelu1(v.y);
            }
        }

        // ---- o = h @ Wm2 + bm2 ; packed accumulators over token pairs ----
        unsigned long long o01x, o23x, o01y, o23y;
        {
            float2 b2 = *(const float2*)(bm2S + 2 * L);
            o01x = o23x = dup2(b2.x);
            o01y = o23y = dup2(b2.y);
        }
        // half 0: channels e in [0,128)
        #pragma unroll
        for (int j = 0; j < 4; j++)
            *(float4*)(hT + hswz(4 * L + j)) = make_float4(hv[j][0], hv[j][1], hv[j][2], hv[j][3]);
        __syncwarp();
        #pragma unroll 4
        for (int e = 0; e < 128; e++) {
            ulonglong2 hp = *(const ulonglong2*)(hT + hswz(e));
            float2 w2 = *(const float2*)(W2S + e * 64 + 2 * L);
            unsigned long long wx = dup2(w2.x), wy = dup2(w2.y);
            o01x = ffma2(hp.x, wx, o01x); o23x = ffma2(hp.y, wx, o23x);
            o01y = ffma2(hp.x, wy, o01y); o23y = ffma2(hp.y, wy, o23y);
        }
        __syncwarp();
        // half 1: channels e in [128,256)
        #pragma unroll
        for (int j = 0; j < 4; j++)
            *(float4*)(hT + hswz(4 * L + j)) = make_float4(hv[4+j][0], hv[4+j][1], hv[4+j][2], hv[4+j][3]);
        __syncwarp();
        #pragma unroll 4
        for (int e = 0; e < 128; e++) {
            ulonglong2 hp = *(const ulonglong2*)(hT + hswz(e));
            float2 w2 = *(const float2*)(W2S + (e + 128) * 64 + 2 * L);
            unsigned long long wx = dup2(w2.x), wy = dup2(w2.y);
            o01x = ffma2(hp.x, wx, o01x); o23x = ffma2(hp.y, wx, o23x);
            o01y = ffma2(hp.x, wy, o01y); o23y = ffma2(hp.y, wy, o23y);
        }

        // ---- shortcut = x @ Ws + bs ; packed ----
        unsigned long long s01x, s23x, s01y, s23y;
        {
            float2 b2 = *(const float2*)(bsS + 2 * L);
            s01x = s23x = dup2(b2.x);
            s01y = s23y = dup2(b2.y);
        }
        #pragma unroll 4
        for (int e = 0; e < 64; e++) {
            ulonglong2 xp = *(const ulonglong2*)(xT + 4 * e);
            float2 ws = *(const float2*)(WsS + e * 64 + 2 * L);
            unsigned long long wx = dup2(ws.x), wy = dup2(ws.y);
            s01x = ffma2(xp.x, wx, s01x); s23x = ffma2(xp.y, wx, s23x);
            s01y = ffma2(xp.x, wy, s01y); s23y = ffma2(xp.y, wy, s23y);
        }

        // unpack accumulators
        float o0[4], o1[4], sc0[4], sc1[4];
        {
            float2 a = unpk2(o01x), bq_ = unpk2(o23x);
            o0[0] = a.x; o0[1] = a.y; o0[2] = bq_.x; o0[3] = bq_.y;
            float2 c = unpk2(o01y), d = unpk2(o23y);
            o1[0] = c.x; o1[1] = c.y; o1[2] = d.x; o1[3] = d.y;
            float2 e_ = unpk2(s01x), f = unpk2(s23x);
            sc0[0] = e_.x; sc0[1] = e_.y; sc0[2] = f.x; sc0[3] = f.y;
            float2 g_ = unpk2(s01y), h_ = unpk2(s23y);
            sc1[0] = g_.x; sc1[1] = g_.y; sc1[2] = h_.x; sc1[3] = h_.y;
        }

        // ---- LN2 (one-pass) + add shortcut, store ----
        #pragma unroll
        for (int t = 0; t < 4; t++) {
            float s1 = warpSum(o0[t] + o1[t]);
            float s2 = warpSum(fmaf(o0[t], o0[t], o1[t] * o1[t]));
            float m2 = s1 * (1.f / 64.f);
            float v2 = fmaf(-m2, m2, s2 * (1.f / 64.f));
            float inv2 = rsqrtf(v2 + 1e-5f);
            float on0 = (o0[t] - m2) * inv2 * g2S[2 * L]     + be2S[2 * L];
            float on1 = (o1[t] - m2) * inv2 * g2S[2 * L + 1] + be2S[2 * L + 1];
            *(float2*)(out + base + t * 64 + 2 * L) = make_float2(on0 + sc0[t], on1 + sc1[t]);
        }
        __syncwarp();   // protect tiles before next group
    }
}

// ===========================================================================
extern "C" void kernel_launch(void* const* d_in, const int* in_sizes, int n_in,
                              void* d_out, int out_size)
{
    const float* u   = (const float*)d_in[0];
    const float* x   = (const float*)d_in[1];
    const float* Wk  = (const float*)d_in[2];
    const float* bk  = (const float*)d_in[3];
    const float* Wq  = (const float*)d_in[4];
    const float* bq  = (const float*)d_in[5];
    const float* Wv  = (const float*)d_in[6];
    const float* bv  = (const float*)d_in[7];
    const float* g1  = (const float*)d_in[8];
    const float* be1 = (const float*)d_in[9];
    const float* Wm1 = (const float*)d_in[10];
    const float* bm1 = (const float*)d_in[11];
    const float* Wm2 = (const float*)d_in[12];
    const float* bm2 = (const float*)d_in[13];
    const float* g2  = (const float*)d_in[14];
    const float* be2 = (const float*)d_in[15];
    const float* Ws  = (const float*)d_in[16];
    const float* bs  = (const float*)d_in[17];
    float* out = (float*)d_out;

    const int smemA = 55936 * 4;   // 223744 B
    const int smemB = 51840 * 4;   // 207360 B
    cudaFuncSetAttribute(attn_kernel, cudaFuncAttributeMaxDynamicSharedMemorySize, smemA);
    cudaFuncSetAttribute(mlp_kernel,  cudaFuncAttributeMaxDynamicSharedMemorySize, smemB);

    attn_kernel<<<GRID, ATHREADS, smemA>>>(u, x, Wk, bk, Wq, bq, Wv, bv);
    mlp_kernel<<<GRID, MTHREADS, smemB>>>(x, g1, be1, Wm1, bm1, Wm2, bm2,
                                          g2, be2, Ws, bs, out);
}